// round 3
// baseline (speedup 1.0000x reference)
#include <cuda_runtime.h>
#include <cuda_bf16.h>
#include <math.h>

#define BATCH 4096
#define FDIM  512
#define NCLS  1000
#define MARGIN 0.3f
#define LAMBDA 0.01f
#define EPSV   1e-12f

// ---------------- device scratch (no allocation allowed) ----------------
__device__ float        g_sq[BATCH];
__device__ int          g_lab[BATCH];
__device__ unsigned int g_ap[BATCH];   // float bits, nonneg -> uint compare OK
__device__ unsigned int g_an[BATCH];
__device__ float        g_ce[BATCH];
__device__ float        g_cent[BATCH];
__device__ int          g_labmode;     // 0 = int64 labels, 1 = int32 labels

// ---------------- label dtype detection ----------------
// Read the first 2048 values as int64 (16KB — safe whether buffer is int32 or
// int64). Genuine int64 labels are all in [0,1000); int32 labels read as int64
// produce packed pairs, nearly all >= 2^32.
__global__ void detect_kernel(const long long* __restrict__ lab64) {
    __shared__ int bad;
    if (threadIdx.x == 0) bad = 0;
    __syncthreads();
    int mybad = 0;
    for (int i = threadIdx.x; i < 2048; i += blockDim.x) {
        long long v = lab64[i];
        if (v < 0 || v >= NCLS) mybad = 1;
    }
    if (mybad) atomicOr(&bad, 1);
    __syncthreads();
    if (threadIdx.x == 0) g_labmode = bad ? 1 : 0;
}

// ---------------- prep: sq norms, label decode, ap/an init ----------------
__global__ void prep_kernel(const float* __restrict__ E, const void* __restrict__ labels) {
    int i = blockIdx.x;
    int t = threadIdx.x;           // 128 threads
    float a = 0.f;
    const float* row = E + (size_t)i * FDIM;
    for (int k = t; k < FDIM; k += 128) { float v = row[k]; a += v * v; }
    // warp reduce
    for (int off = 16; off > 0; off >>= 1) a += __shfl_xor_sync(0xffffffff, a, off);
    __shared__ float wsum[4];
    if ((t & 31) == 0) wsum[t >> 5] = a;
    __syncthreads();
    if (t == 0) {
        float s = wsum[0] + wsum[1] + wsum[2] + wsum[3];
        g_sq[i] = s;
        int lab;
        if (g_labmode == 0) lab = (int)((const long long*)labels)[i];
        else                lab = ((const int*)labels)[i];
        g_lab[i] = lab;
        g_ap[i] = 0u;           // 0.0f
        g_an[i] = 0x7f800000u;  // +inf
    }
}

// ---------------- triplet: fused Gram + hardest pos/neg ----------------
// 64x64 tile per block, 4x4 per thread, K-chunks of 32 held transposed in smem.
// grid (64, 4): blockIdx.x = i-tile, blockIdx.y = quarter of j range.
__global__ __launch_bounds__(256) void triplet_kernel(const float* __restrict__ E) {
    const int TI = 64, TJ = 64, TK = 32;
    __shared__ float sAT[TK][TI + 4];
    __shared__ float sBT[TK][TJ + 4];
    __shared__ float sQi[TI]; __shared__ int sLi[TI];
    __shared__ float sQj[TJ]; __shared__ int sLj[TJ];

    int t  = threadIdx.x;
    int tx = t & 15;       // 16 * 4 = 64 j-cols
    int ty = t >> 4;       // 16 * 4 = 64 i-rows
    int i0 = blockIdx.x * TI;
    int jbase = blockIdx.y * (BATCH / 4);

    if (t < TI) { sQi[t] = g_sq[i0 + t]; sLi[t] = g_lab[i0 + t]; }

    float ap[4] = {0.f, 0.f, 0.f, 0.f};
    float an[4] = {INFINITY, INFINITY, INFINITY, INFINITY};

    for (int j0 = jbase; j0 < jbase + BATCH / 4; j0 += TJ) {
        __syncthreads();   // previous-iteration readers of sQj/sLj done
        if (t < TJ) { sQj[t] = g_sq[j0 + t]; sLj[t] = g_lab[j0 + t]; }

        float acc[4][4];
        #pragma unroll
        for (int r = 0; r < 4; r++)
            #pragma unroll
            for (int c = 0; c < 4; c++) acc[r][c] = 0.f;

        for (int k0 = 0; k0 < FDIM; k0 += TK) {
            __syncthreads();
            #pragma unroll
            for (int s = 0; s < 2; s++) {
                int f = t + s * 256;
                int row = f >> 3;
                int c4  = (f & 7) * 4;
                float4 va = *(const float4*)&E[(size_t)(i0 + row) * FDIM + k0 + c4];
                sAT[c4 + 0][row] = va.x; sAT[c4 + 1][row] = va.y;
                sAT[c4 + 2][row] = va.z; sAT[c4 + 3][row] = va.w;
                float4 vb = *(const float4*)&E[(size_t)(j0 + row) * FDIM + k0 + c4];
                sBT[c4 + 0][row] = vb.x; sBT[c4 + 1][row] = vb.y;
                sBT[c4 + 2][row] = vb.z; sBT[c4 + 3][row] = vb.w;
            }
            __syncthreads();
            #pragma unroll
            for (int kk = 0; kk < TK; kk++) {
                float4 a = *(float4*)&sAT[kk][ty * 4];
                float4 b = *(float4*)&sBT[kk][tx * 4];
                acc[0][0] += a.x * b.x; acc[0][1] += a.x * b.y; acc[0][2] += a.x * b.z; acc[0][3] += a.x * b.w;
                acc[1][0] += a.y * b.x; acc[1][1] += a.y * b.y; acc[1][2] += a.y * b.z; acc[1][3] += a.y * b.w;
                acc[2][0] += a.z * b.x; acc[2][1] += a.z * b.y; acc[2][2] += a.z * b.z; acc[2][3] += a.z * b.w;
                acc[3][0] += a.w * b.x; acc[3][1] += a.w * b.y; acc[3][2] += a.w * b.z; acc[3][3] += a.w * b.w;
            }
        }
        __syncthreads();   // sAT/sBT consumers done; also orders sQj/sLj reads below
        #pragma unroll
        for (int r = 0; r < 4; r++) {
            int   li = sLi[ty * 4 + r];
            float qi = sQi[ty * 4 + r];
            #pragma unroll
            for (int c = 0; c < 4; c++) {
                float d2 = qi + sQj[tx * 4 + c] - 2.f * acc[r][c];
                float dist = sqrtf(fmaxf(d2, EPSV));
                if (sLj[tx * 4 + c] == li) ap[r] = fmaxf(ap[r], dist);
                else                       an[r] = fminf(an[r], dist);
            }
        }
    }

    // reduce over tx (lane bits 0..3)
    #pragma unroll
    for (int off = 1; off < 16; off <<= 1) {
        #pragma unroll
        for (int r = 0; r < 4; r++) {
            ap[r] = fmaxf(ap[r], __shfl_xor_sync(0xffffffff, ap[r], off));
            an[r] = fminf(an[r], __shfl_xor_sync(0xffffffff, an[r], off));
        }
    }
    if (tx == 0) {
        #pragma unroll
        for (int r = 0; r < 4; r++) {
            int i = i0 + ty * 4 + r;
            atomicMax(&g_ap[i], __float_as_uint(ap[r]));
            atomicMin(&g_an[i], __float_as_uint(an[r]));
        }
    }
}

// ---------------- CE: logits GEMM + online logsumexp ----------------
// 16 rows per block (grid 256), class chunks of 40, 128 threads.
__global__ __launch_bounds__(128) void ce_kernel(const float* __restrict__ E,
                                                 const float* __restrict__ W,
                                                 const float* __restrict__ bvec) {
    const int TI = 16, NC = 40, TK = 32;
    __shared__ float sET[TK][TI + 1];
    __shared__ float sWT[TK][NC + 2];
    __shared__ float sLog[TI][NC + 1];
    __shared__ float sM[TI], sS[TI], sRef[TI];

    int t   = threadIdx.x;
    int row = t & 15;
    int cg  = t >> 4;       // 8 groups of 5 classes
    int i0  = blockIdx.x * TI;

    if (t < TI) { sM[t] = -INFINITY; sS[t] = 0.f; sRef[t] = 0.f; }

    for (int c0 = 0; c0 < NCLS; c0 += NC) {
        float acc[5] = {0.f, 0.f, 0.f, 0.f, 0.f};
        for (int k0 = 0; k0 < FDIM; k0 += TK) {
            __syncthreads();
            {
                int f = t;                     // 128 threads * 1 float4 = 16x32
                int r = f >> 3, c4 = (f & 7) * 4;
                float4 v = *(const float4*)&E[(size_t)(i0 + r) * FDIM + k0 + c4];
                sET[c4 + 0][r] = v.x; sET[c4 + 1][r] = v.y;
                sET[c4 + 2][r] = v.z; sET[c4 + 3][r] = v.w;
            }
            #pragma unroll
            for (int s = 0; s < 3; s++) {
                int f = t + s * 128;           // 320 float4 = 40x32
                if (f < 320) {
                    int cls = f >> 3, c4 = (f & 7) * 4;
                    float4 v = *(const float4*)&W[(size_t)(c0 + cls) * FDIM + k0 + c4];
                    sWT[c4 + 0][cls] = v.x; sWT[c4 + 1][cls] = v.y;
                    sWT[c4 + 2][cls] = v.z; sWT[c4 + 3][cls] = v.w;
                }
            }
            __syncthreads();
            #pragma unroll
            for (int kk = 0; kk < TK; kk++) {
                float a = sET[kk][row];
                #pragma unroll
                for (int q = 0; q < 5; q++)
                    acc[q] += a * sWT[kk][cg * 5 + q];
            }
        }
        __syncthreads();
        #pragma unroll
        for (int q = 0; q < 5; q++)
            sLog[row][cg * 5 + q] = acc[q] + bvec[c0 + cg * 5 + q];
        __syncthreads();
        if (t < TI) {
            int lab = g_lab[i0 + t];
            float m = sM[t], s = sS[t];
            for (int c = 0; c < NC; c++) {
                float v = sLog[t][c];
                if (v > m) { s = s * expf(m - v) + 1.f; m = v; }
                else       { s += expf(v - m); }
                if (c0 + c == lab) sRef[t] = v;
            }
            sM[t] = m; sS[t] = s;
        }
    }
    if (t < TI)
        g_ce[i0 + t] = sM[t] + logf(sS[t]) - sRef[t];
}

// ---------------- center loss ----------------
__global__ void center_kernel(const float* __restrict__ E, const float* __restrict__ Ctr) {
    int i = blockIdx.x;
    int t = threadIdx.x;   // 128
    int lab = g_lab[i];
    const float* e = E   + (size_t)i   * FDIM;
    const float* c = Ctr + (size_t)lab * FDIM;
    float a = 0.f;
    for (int k = t; k < FDIM; k += 128) { float d = e[k] - c[k]; a += d * d; }
    for (int off = 16; off > 0; off >>= 1) a += __shfl_xor_sync(0xffffffff, a, off);
    __shared__ float wsum[4];
    if ((t & 31) == 0) wsum[t >> 5] = a;
    __syncthreads();
    if (t == 0) g_cent[i] = wsum[0] + wsum[1] + wsum[2] + wsum[3];
}

// ---------------- final deterministic reduction ----------------
__global__ void final_kernel(float* __restrict__ out) {
    int t = threadIdx.x;   // 256
    float l = 0.f;
    for (int i = t; i < BATCH; i += 256) {
        float ap = __uint_as_float(g_ap[i]);
        float an = __uint_as_float(g_an[i]);
        l += fmaxf(ap - an + MARGIN, 0.f) + LAMBDA * g_cent[i] + g_ce[i];
    }
    __shared__ float red[256];
    red[t] = l;
    __syncthreads();
    for (int off = 128; off > 0; off >>= 1) {
        if (t < off) red[t] += red[t + off];
        __syncthreads();
    }
    if (t == 0) out[0] = red[0] / (float)BATCH;
}

// ---------------- launch ----------------
extern "C" void kernel_launch(void* const* d_in, const int* in_sizes, int n_in,
                              void* d_out, int out_size) {
    const float* E    = (const float*)d_in[0];
    const void*  labs = d_in[1];
    const float* Ctr  = (const float*)d_in[2];
    const float* W    = (const float*)d_in[3];
    const float* bvec = (const float*)d_in[4];
    float* out = (float*)d_out;

    detect_kernel<<<1, 256>>>((const long long*)labs);
    prep_kernel<<<BATCH, 128>>>(E, labs);
    triplet_kernel<<<dim3(BATCH / 64, 4), 256>>>(E);
    ce_kernel<<<BATCH / 16, 128>>>(E, W, bvec);
    center_kernel<<<BATCH, 128>>>(E, Ctr);
    final_kernel<<<1, 256>>>(out);
}

// round 4
// speedup vs baseline: 2.0718x; 2.0718x over previous
#include <cuda_runtime.h>
#include <cuda_bf16.h>
#include <math.h>

#define BATCH 4096
#define FDIM  512
#define NCLS  1000
#define NCPAD 1024
#define MARGIN 0.3f
#define LAMBDA 0.01f
#define EPSV   1e-12f
#define NJT   8          // class j-tiles of 128

// ---------------- device scratch (no allocation allowed) ----------------
__device__ float        g_sq[BATCH];
__device__ int          g_lab[BATCH];
__device__ unsigned int g_ap[BATCH];     // float bits, nonneg -> uint compare OK
__device__ unsigned int g_an[BATCH];
__device__ float        g_ce[BATCH];
__device__ float        g_cent[BATCH];
__device__ float        g_pm[BATCH][NJT];  // partial logsumexp max
__device__ float        g_ps[BATCH][NJT];  // partial logsumexp sum
__device__ float        g_ref[BATCH];      // logit of true class
__device__ int          g_labmode;         // 0 = int64 labels, 1 = int32 labels

// ---------------- label dtype detection ----------------
__global__ void detect_kernel(const long long* __restrict__ lab64) {
    __shared__ int bad;
    if (threadIdx.x == 0) bad = 0;
    __syncthreads();
    int mybad = 0;
    for (int i = threadIdx.x; i < 2048; i += blockDim.x) {
        long long v = lab64[i];
        if (v < 0 || v >= NCLS) mybad = 1;
    }
    if (mybad) atomicOr(&bad, 1);
    __syncthreads();
    if (threadIdx.x == 0) g_labmode = bad ? 1 : 0;
}

// ---------------- prep: sq norms, label decode, ap/an init ----------------
__global__ void prep_kernel(const float* __restrict__ E, const void* __restrict__ labels) {
    int i = blockIdx.x;
    int t = threadIdx.x;           // 128 threads
    float a = 0.f;
    const float* row = E + (size_t)i * FDIM;
    for (int k = t; k < FDIM; k += 128) { float v = row[k]; a += v * v; }
    for (int off = 16; off > 0; off >>= 1) a += __shfl_xor_sync(0xffffffff, a, off);
    __shared__ float wsum[4];
    if ((t & 31) == 0) wsum[t >> 5] = a;
    __syncthreads();
    if (t == 0) {
        float s = wsum[0] + wsum[1] + wsum[2] + wsum[3];
        g_sq[i] = s;
        int lab;
        if (g_labmode == 0) lab = (int)((const long long*)labels)[i];
        else                lab = ((const int*)labels)[i];
        g_lab[i] = lab;
        g_ap[i] = 0u;           // 0.0f
        g_an[i] = 0x7f800000u;  // +inf
    }
}

// ---------------- triplet: fused Gram + hardest pos/neg ----------------
// 128x128 tile, 8x8 per thread (16x16 threads), TK=16.
// grid (32, 8): i-tile x j-eighth (512 j per block = 4 tiles).
__global__ __launch_bounds__(256) void triplet_kernel(const float* __restrict__ E) {
    const int TI = 128, TJ = 128, TK = 16;
    __shared__ float sAT[TK][TI + 4];
    __shared__ float sBT[TK][TJ + 4];
    __shared__ float sQi[TI]; __shared__ int sLi[TI];
    __shared__ float sQj[TJ]; __shared__ int sLj[TJ];

    int t  = threadIdx.x;
    int tx = t & 15;       // 16 * 8 = 128 j-cols
    int ty = t >> 4;       // 16 * 8 = 128 i-rows
    int i0 = blockIdx.x * TI;
    int jbase = blockIdx.y * (BATCH / 8);

    if (t < TI) { sQi[t] = g_sq[i0 + t]; sLi[t] = g_lab[i0 + t]; }

    float ap[8], an[8];
    #pragma unroll
    for (int r = 0; r < 8; r++) { ap[r] = 0.f; an[r] = INFINITY; }

    for (int j0 = jbase; j0 < jbase + BATCH / 8; j0 += TJ) {
        __syncthreads();   // previous epilogue readers of sQj/sLj done
        if (t < TJ) { sQj[t] = g_sq[j0 + t]; sLj[t] = g_lab[j0 + t]; }

        float acc[8][8];
        #pragma unroll
        for (int r = 0; r < 8; r++)
            #pragma unroll
            for (int c = 0; c < 8; c++) acc[r][c] = 0.f;

        for (int k0 = 0; k0 < FDIM; k0 += TK) {
            __syncthreads();
            #pragma unroll
            for (int s = 0; s < 2; s++) {
                int f = t + s * 256;       // 512 float4 per tile
                int row = f >> 2;
                int c4  = (f & 3) * 4;
                float4 va = *(const float4*)&E[(size_t)(i0 + row) * FDIM + k0 + c4];
                sAT[c4 + 0][row] = va.x; sAT[c4 + 1][row] = va.y;
                sAT[c4 + 2][row] = va.z; sAT[c4 + 3][row] = va.w;
                float4 vb = *(const float4*)&E[(size_t)(j0 + row) * FDIM + k0 + c4];
                sBT[c4 + 0][row] = vb.x; sBT[c4 + 1][row] = vb.y;
                sBT[c4 + 2][row] = vb.z; sBT[c4 + 3][row] = vb.w;
            }
            __syncthreads();
            #pragma unroll
            for (int kk = 0; kk < TK; kk++) {
                float a[8], b[8];
                *(float4*)&a[0] = *(float4*)&sAT[kk][ty * 8];
                *(float4*)&a[4] = *(float4*)&sAT[kk][ty * 8 + 4];
                *(float4*)&b[0] = *(float4*)&sBT[kk][tx * 8];
                *(float4*)&b[4] = *(float4*)&sBT[kk][tx * 8 + 4];
                #pragma unroll
                for (int r = 0; r < 8; r++)
                    #pragma unroll
                    for (int c = 0; c < 8; c++)
                        acc[r][c] += a[r] * b[c];
            }
        }
        __syncthreads();   // smem consumers done before next tile overwrites
        #pragma unroll
        for (int r = 0; r < 8; r++) {
            int   li = sLi[ty * 8 + r];
            float qi = sQi[ty * 8 + r];
            #pragma unroll
            for (int c = 0; c < 8; c++) {
                float d2 = qi + sQj[tx * 8 + c] - 2.f * acc[r][c];
                float dist = sqrtf(fmaxf(d2, EPSV));
                if (sLj[tx * 8 + c] == li) ap[r] = fmaxf(ap[r], dist);
                else                       an[r] = fminf(an[r], dist);
            }
        }
    }

    // reduce over tx (lane bits 0..3)
    #pragma unroll
    for (int off = 1; off < 16; off <<= 1) {
        #pragma unroll
        for (int r = 0; r < 8; r++) {
            ap[r] = fmaxf(ap[r], __shfl_xor_sync(0xffffffff, ap[r], off));
            an[r] = fminf(an[r], __shfl_xor_sync(0xffffffff, an[r], off));
        }
    }
    if (tx == 0) {
        #pragma unroll
        for (int r = 0; r < 8; r++) {
            int i = i0 + ty * 8 + r;
            atomicMax(&g_ap[i], __float_as_uint(ap[r]));
            atomicMin(&g_an[i], __float_as_uint(an[r]));
        }
    }
}

// ---------------- CE tile: logits GEMM + per-tile partial logsumexp ----------------
// 128x128 tile, 8x8 per thread, TK=16. grid (32, 8). Cols padded 1000->1024.
__global__ __launch_bounds__(256) void ce_tile_kernel(const float* __restrict__ E,
                                                      const float* __restrict__ W,
                                                      const float* __restrict__ bvec) {
    const int TI = 128, TJ = 128, TK = 16;
    __shared__ float sAT[TK][TI + 4];
    __shared__ float sBT[TK][TJ + 4];
    __shared__ float sBias[TJ];
    __shared__ int   sLab[TI];

    int t  = threadIdx.x;
    int tx = t & 15;
    int ty = t >> 4;
    int i0 = blockIdx.x * TI;
    int j0 = blockIdx.y * TJ;
    int jt = blockIdx.y;

    if (t < TJ) { int cls = j0 + t; sBias[t] = bvec[cls < NCLS ? cls : NCLS - 1]; }
    else if (t < TJ + TI) { sLab[t - TJ] = g_lab[i0 + (t - TJ)]; }

    float acc[8][8];
    #pragma unroll
    for (int r = 0; r < 8; r++)
        #pragma unroll
        for (int c = 0; c < 8; c++) acc[r][c] = 0.f;

    for (int k0 = 0; k0 < FDIM; k0 += TK) {
        __syncthreads();
        #pragma unroll
        for (int s = 0; s < 2; s++) {
            int f = t + s * 256;
            int row = f >> 2;
            int c4  = (f & 3) * 4;
            float4 va = *(const float4*)&E[(size_t)(i0 + row) * FDIM + k0 + c4];
            sAT[c4 + 0][row] = va.x; sAT[c4 + 1][row] = va.y;
            sAT[c4 + 2][row] = va.z; sAT[c4 + 3][row] = va.w;
            int wrow = j0 + row; if (wrow >= NCLS) wrow = NCLS - 1;  // clamp, masked later
            float4 vb = *(const float4*)&W[(size_t)wrow * FDIM + k0 + c4];
            sBT[c4 + 0][row] = vb.x; sBT[c4 + 1][row] = vb.y;
            sBT[c4 + 2][row] = vb.z; sBT[c4 + 3][row] = vb.w;
        }
        __syncthreads();
        #pragma unroll
        for (int kk = 0; kk < TK; kk++) {
            float a[8], b[8];
            *(float4*)&a[0] = *(float4*)&sAT[kk][ty * 8];
            *(float4*)&a[4] = *(float4*)&sAT[kk][ty * 8 + 4];
            *(float4*)&b[0] = *(float4*)&sBT[kk][tx * 8];
            *(float4*)&b[4] = *(float4*)&sBT[kk][tx * 8 + 4];
            #pragma unroll
            for (int r = 0; r < 8; r++)
                #pragma unroll
                for (int c = 0; c < 8; c++)
                    acc[r][c] += a[r] * b[c];
        }
    }
    __syncthreads();

    // epilogue: v = acc + bias (masked); per-row partial (max, sumexp) over 128 cols
    #pragma unroll
    for (int r = 0; r < 8; r++) {
        int irow = i0 + ty * 8 + r;
        int lab  = sLab[ty * 8 + r];
        float v[8];
        float m = -INFINITY;
        #pragma unroll
        for (int c = 0; c < 8; c++) {
            int col = j0 + tx * 8 + c;
            v[c] = (col < NCLS) ? (acc[r][c] + sBias[tx * 8 + c]) : -INFINITY;
            if (col == lab) g_ref[irow] = v[c];   // exactly one writer per row
            m = fmaxf(m, v[c]);
        }
        #pragma unroll
        for (int off = 1; off < 16; off <<= 1)
            m = fmaxf(m, __shfl_xor_sync(0xffffffff, m, off));
        float s = 0.f;
        #pragma unroll
        for (int c = 0; c < 8; c++) s += __expf(v[c] - m);
        #pragma unroll
        for (int off = 1; off < 16; off <<= 1)
            s += __shfl_xor_sync(0xffffffff, s, off);
        if (tx == 0) { g_pm[irow][jt] = m; g_ps[irow][jt] = s; }
    }
}

// ---------------- CE merge: combine 8 partials per row ----------------
__global__ void ce_merge_kernel() {
    int i = blockIdx.x * blockDim.x + threadIdx.x;
    if (i >= BATCH) return;
    float M = -INFINITY;
    #pragma unroll
    for (int k = 0; k < NJT; k++) M = fmaxf(M, g_pm[i][k]);
    float S = 0.f;
    #pragma unroll
    for (int k = 0; k < NJT; k++) S += g_ps[i][k] * expf(g_pm[i][k] - M);
    g_ce[i] = M + logf(S) - g_ref[i];
}

// ---------------- center loss ----------------
__global__ void center_kernel(const float* __restrict__ E, const float* __restrict__ Ctr) {
    int i = blockIdx.x;
    int t = threadIdx.x;   // 128
    int lab = g_lab[i];
    const float* e = E   + (size_t)i   * FDIM;
    const float* c = Ctr + (size_t)lab * FDIM;
    float a = 0.f;
    for (int k = t; k < FDIM; k += 128) { float d = e[k] - c[k]; a += d * d; }
    for (int off = 16; off > 0; off >>= 1) a += __shfl_xor_sync(0xffffffff, a, off);
    __shared__ float wsum[4];
    if ((t & 31) == 0) wsum[t >> 5] = a;
    __syncthreads();
    if (t == 0) g_cent[i] = wsum[0] + wsum[1] + wsum[2] + wsum[3];
}

// ---------------- final deterministic reduction ----------------
__global__ void final_kernel(float* __restrict__ out) {
    int t = threadIdx.x;   // 256
    float l = 0.f;
    for (int i = t; i < BATCH; i += 256) {
        float ap = __uint_as_float(g_ap[i]);
        float an = __uint_as_float(g_an[i]);
        l += fmaxf(ap - an + MARGIN, 0.f) + LAMBDA * g_cent[i] + g_ce[i];
    }
    __shared__ float red[256];
    red[t] = l;
    __syncthreads();
    for (int off = 128; off > 0; off >>= 1) {
        if (t < off) red[t] += red[t + off];
        __syncthreads();
    }
    if (t == 0) out[0] = red[0] / (float)BATCH;
}

// ---------------- launch ----------------
extern "C" void kernel_launch(void* const* d_in, const int* in_sizes, int n_in,
                              void* d_out, int out_size) {
    const float* E    = (const float*)d_in[0];
    const void*  labs = d_in[1];
    const float* Ctr  = (const float*)d_in[2];
    const float* W    = (const float*)d_in[3];
    const float* bvec = (const float*)d_in[4];
    float* out = (float*)d_out;

    detect_kernel<<<1, 256>>>((const long long*)labs);
    prep_kernel<<<BATCH, 128>>>(E, labs);
    triplet_kernel<<<dim3(BATCH / 128, 8), 256>>>(E);
    ce_tile_kernel<<<dim3(BATCH / 128, NJT), 256>>>(E, W, bvec);
    ce_merge_kernel<<<BATCH / 256, 256>>>();
    center_kernel<<<BATCH, 128>>>(E, Ctr);
    final_kernel<<<1, 256>>>(out);
}

// round 6
// speedup vs baseline: 6.1394x; 2.9632x over previous
#include <cuda_runtime.h>
#include <cuda_bf16.h>
#include <math.h>
#include <stdint.h>

#define BATCH 4096
#define FDIM  512
#define NCLS  1000
#define MARGIN 0.3f
#define LAMBDA 0.01f
#define EPSV   1e-12f
#define NJT2  16         // CE partials per row: 8 j-tiles x 2 warp-halves

// ---------------- device scratch ----------------
__device__ float        g_sq[BATCH];
__device__ int          g_lab[BATCH];
__device__ unsigned int g_ap[BATCH];
__device__ unsigned int g_an[BATCH];
__device__ float        g_ce[BATCH];
__device__ float        g_cent[BATCH];
__device__ float        g_pm[BATCH][NJT2];
__device__ float        g_ps[BATCH][NJT2];
__device__ float        g_ref[BATCH];
__device__ int          g_labmode;

// ---------------- helpers ----------------
__device__ __forceinline__ float to_tf32(float x) {
    uint32_t u;
    asm("cvt.rna.tf32.f32 %0, %1;" : "=r"(u) : "f"(x));
    return __uint_as_float(u);
}
__device__ __forceinline__ void mma_tf32(float* c, const uint32_t* a, uint32_t b0, uint32_t b1) {
    asm volatile(
        "mma.sync.aligned.m16n8k8.row.col.f32.tf32.tf32.f32 "
        "{%0,%1,%2,%3}, {%4,%5,%6,%7}, {%8,%9}, {%0,%1,%2,%3};"
        : "+f"(c[0]), "+f"(c[1]), "+f"(c[2]), "+f"(c[3])
        : "r"(a[0]), "r"(a[1]), "r"(a[2]), "r"(a[3]), "r"(b0), "r"(b1));
}

// ---------------- label dtype detection ----------------
__global__ void detect_kernel(const long long* __restrict__ lab64) {
    __shared__ int bad;
    if (threadIdx.x == 0) bad = 0;
    __syncthreads();
    int mybad = 0;
    for (int i = threadIdx.x; i < 2048; i += blockDim.x) {
        long long v = lab64[i];
        if (v < 0 || v >= NCLS) mybad = 1;
    }
    if (mybad) atomicOr(&bad, 1);
    __syncthreads();
    if (threadIdx.x == 0) g_labmode = bad ? 1 : 0;
}

// ---------------- prep ----------------
__global__ void prep_kernel(const float* __restrict__ E, const void* __restrict__ labels) {
    int i = blockIdx.x;
    int t = threadIdx.x;
    float a = 0.f;
    const float* row = E + (size_t)i * FDIM;
    for (int k = t; k < FDIM; k += 128) { float v = row[k]; a += v * v; }
    for (int off = 16; off > 0; off >>= 1) a += __shfl_xor_sync(0xffffffff, a, off);
    __shared__ float wsum[4];
    if ((t & 31) == 0) wsum[t >> 5] = a;
    __syncthreads();
    if (t == 0) {
        g_sq[i] = wsum[0] + wsum[1] + wsum[2] + wsum[3];
        int lab;
        if (g_labmode == 0) lab = (int)((const long long*)labels)[i];
        else                lab = ((const int*)labels)[i];
        g_lab[i] = lab;
        g_ap[i] = 0u;
        g_an[i] = 0x7f800000u;
    }
}

// ---------------- triplet: tf32 mma.sync Gram + fused ap/an ----------------
// Block tile 128x128, 8 warps (4x2), warp tile 32x64, K-chunks of 32.
#define BM 128
#define BN 128
#define BK 32
#define SSTR 36   // smem row stride (floats); fragment LDS bank = 4g+tg, conflict-free

__global__ __launch_bounds__(256) void triplet_mma_kernel(const float* __restrict__ E) {
    __shared__ float sA[BM][SSTR];
    __shared__ float sB[BN][SSTR];
    __shared__ float sQi[BM]; __shared__ int sLi[BM];
    __shared__ float sQj[BN]; __shared__ int sLj[BN];

    int t = threadIdx.x;
    int lane = t & 31, wid = t >> 5;
    int wm = wid >> 1, wn = wid & 1;
    int g = lane >> 2, tg = lane & 3;
    int i0 = blockIdx.x * BM, j0 = blockIdx.y * BN;

    if (t < BM)            { sQi[t] = g_sq[i0 + t]; sLi[t] = g_lab[i0 + t]; }
    else if (t < BM + BN)  { int u = t - BM; sQj[u] = g_sq[j0 + u]; sLj[u] = g_lab[j0 + u]; }

    float acc[2][8][4];
    #pragma unroll
    for (int mt = 0; mt < 2; mt++)
        #pragma unroll
        for (int nt = 0; nt < 8; nt++)
            #pragma unroll
            for (int e = 0; e < 4; e++) acc[mt][nt][e] = 0.f;

    for (int k0 = 0; k0 < FDIM; k0 += BK) {
        __syncthreads();
        #pragma unroll
        for (int s = 0; s < 4; s++) {       // 1024 float4 each for A and B
            int f = t + s * 256;
            int r = f >> 3, q = (f & 7) * 4;
            float4 v = *(const float4*)&E[(size_t)(i0 + r) * FDIM + k0 + q];
            float* da = &sA[r][q];
            da[0] = to_tf32(v.x); da[1] = to_tf32(v.y); da[2] = to_tf32(v.z); da[3] = to_tf32(v.w);
            float4 w = *(const float4*)&E[(size_t)(j0 + r) * FDIM + k0 + q];
            float* db = &sB[r][q];
            db[0] = to_tf32(w.x); db[1] = to_tf32(w.y); db[2] = to_tf32(w.z); db[3] = to_tf32(w.w);
        }
        __syncthreads();
        #pragma unroll
        for (int k8 = 0; k8 < 4; k8++) {
            int c = k8 * 8;
            uint32_t af[2][4];
            #pragma unroll
            for (int mt = 0; mt < 2; mt++) {
                int r = wm * 32 + mt * 16;
                af[mt][0] = __float_as_uint(sA[r + g    ][c + tg    ]);
                af[mt][1] = __float_as_uint(sA[r + g + 8][c + tg    ]);
                af[mt][2] = __float_as_uint(sA[r + g    ][c + tg + 4]);
                af[mt][3] = __float_as_uint(sA[r + g + 8][c + tg + 4]);
            }
            #pragma unroll
            for (int nt = 0; nt < 8; nt++) {
                int rn = wn * 64 + nt * 8;
                uint32_t b0 = __float_as_uint(sB[rn + g][c + tg    ]);
                uint32_t b1 = __float_as_uint(sB[rn + g][c + tg + 4]);
                mma_tf32(acc[0][nt], af[0], b0, b1);
                mma_tf32(acc[1][nt], af[1], b0, b1);
            }
        }
    }

    // epilogue: dist + hardest pos/neg. C frag: c0=C[g][2tg] c1=C[g][2tg+1] c2=C[g+8][..]
    #pragma unroll
    for (int mt = 0; mt < 2; mt++) {
        #pragma unroll
        for (int half = 0; half < 2; half++) {
            int lr = wm * 32 + mt * 16 + g + half * 8;
            float qi = sQi[lr]; int li = sLi[lr];
            float ap = 0.f, an = INFINITY;
            #pragma unroll
            for (int nt = 0; nt < 8; nt++) {
                #pragma unroll
                for (int e = 0; e < 2; e++) {
                    int lc = wn * 64 + nt * 8 + 2 * tg + e;
                    float d2 = qi + sQj[lc] - 2.f * acc[mt][nt][half * 2 + e];
                    float dist = sqrtf(fmaxf(d2, EPSV));
                    if (sLj[lc] == li) ap = fmaxf(ap, dist);
                    else               an = fminf(an, dist);
                }
            }
            ap = fmaxf(ap, __shfl_xor_sync(0xffffffff, ap, 1));
            ap = fmaxf(ap, __shfl_xor_sync(0xffffffff, ap, 2));
            an = fminf(an, __shfl_xor_sync(0xffffffff, an, 1));
            an = fminf(an, __shfl_xor_sync(0xffffffff, an, 2));
            if (tg == 0) {
                atomicMax(&g_ap[i0 + lr], __float_as_uint(ap));
                atomicMin(&g_an[i0 + lr], __float_as_uint(an));
            }
        }
    }
}

// ---------------- CE: tf32 mma.sync logits + partial logsumexp ----------------
__global__ __launch_bounds__(256) void ce_mma_kernel(const float* __restrict__ E,
                                                     const float* __restrict__ W,
                                                     const float* __restrict__ bvec) {
    __shared__ float sA[BM][SSTR];
    __shared__ float sB[BN][SSTR];
    __shared__ float sBias[BN];
    __shared__ int   sLab[BM];

    int t = threadIdx.x;
    int lane = t & 31, wid = t >> 5;
    int wm = wid >> 1, wn = wid & 1;
    int g = lane >> 2, tg = lane & 3;
    int i0 = blockIdx.x * BM, j0 = blockIdx.y * BN;
    int jt = blockIdx.y;

    if (t < BN)           { int cls = j0 + t; sBias[t] = bvec[cls < NCLS ? cls : NCLS - 1]; }
    else if (t < BN + BM) { sLab[t - BN] = g_lab[i0 + (t - BN)]; }

    float acc[2][8][4];
    #pragma unroll
    for (int mt = 0; mt < 2; mt++)
        #pragma unroll
        for (int nt = 0; nt < 8; nt++)
            #pragma unroll
            for (int e = 0; e < 4; e++) acc[mt][nt][e] = 0.f;

    for (int k0 = 0; k0 < FDIM; k0 += BK) {
        __syncthreads();
        #pragma unroll
        for (int s = 0; s < 4; s++) {
            int f = t + s * 256;
            int r = f >> 3, q = (f & 7) * 4;
            float4 v = *(const float4*)&E[(size_t)(i0 + r) * FDIM + k0 + q];
            float* da = &sA[r][q];
            da[0] = to_tf32(v.x); da[1] = to_tf32(v.y); da[2] = to_tf32(v.z); da[3] = to_tf32(v.w);
            int wr = j0 + r; if (wr >= NCLS) wr = NCLS - 1;    // clamp; masked later
            float4 w = *(const float4*)&W[(size_t)wr * FDIM + k0 + q];
            float* db = &sB[r][q];
            db[0] = to_tf32(w.x); db[1] = to_tf32(w.y); db[2] = to_tf32(w.z); db[3] = to_tf32(w.w);
        }
        __syncthreads();
        #pragma unroll
        for (int k8 = 0; k8 < 4; k8++) {
            int c = k8 * 8;
            uint32_t af[2][4];
            #pragma unroll
            for (int mt = 0; mt < 2; mt++) {
                int r = wm * 32 + mt * 16;
                af[mt][0] = __float_as_uint(sA[r + g    ][c + tg    ]);
                af[mt][1] = __float_as_uint(sA[r + g + 8][c + tg    ]);
                af[mt][2] = __float_as_uint(sA[r + g    ][c + tg + 4]);
                af[mt][3] = __float_as_uint(sA[r + g + 8][c + tg + 4]);
            }
            #pragma unroll
            for (int nt = 0; nt < 8; nt++) {
                int rn = wn * 64 + nt * 8;
                uint32_t b0 = __float_as_uint(sB[rn + g][c + tg    ]);
                uint32_t b1 = __float_as_uint(sB[rn + g][c + tg + 4]);
                mma_tf32(acc[0][nt], af[0], b0, b1);
                mma_tf32(acc[1][nt], af[1], b0, b1);
            }
        }
    }

    // epilogue: masked bias-add, per-(row, warp) partial (max, sumexp) over 64 cols
    #pragma unroll
    for (int mt = 0; mt < 2; mt++) {
        #pragma unroll
        for (int half = 0; half < 2; half++) {
            int lr = wm * 32 + mt * 16 + g + half * 8;
            int irow = i0 + lr;
            int lab  = sLab[lr];
            float v[16];
            float m = -INFINITY;
            #pragma unroll
            for (int nt = 0; nt < 8; nt++) {
                #pragma unroll
                for (int e = 0; e < 2; e++) {
                    int lc  = wn * 64 + nt * 8 + 2 * tg + e;
                    int col = j0 + lc;
                    float x = (col < NCLS) ? (acc[mt][nt][half * 2 + e] + sBias[lc]) : -INFINITY;
                    if (col == lab) g_ref[irow] = x;
                    v[nt * 2 + e] = x;
                    m = fmaxf(m, x);
                }
            }
            m = fmaxf(m, __shfl_xor_sync(0xffffffff, m, 1));
            m = fmaxf(m, __shfl_xor_sync(0xffffffff, m, 2));
            float s = 0.f;
            #pragma unroll
            for (int q = 0; q < 16; q++) s += __expf(v[q] - m);
            s += __shfl_xor_sync(0xffffffff, s, 1);
            s += __shfl_xor_sync(0xffffffff, s, 2);
            if (tg == 0) { g_pm[irow][jt * 2 + wn] = m; g_ps[irow][jt * 2 + wn] = s; }
        }
    }
}

// ---------------- CE merge ----------------
__global__ void ce_merge_kernel() {
    int i = blockIdx.x * blockDim.x + threadIdx.x;
    if (i >= BATCH) return;
    float M = -INFINITY;
    #pragma unroll
    for (int k = 0; k < NJT2; k++) M = fmaxf(M, g_pm[i][k]);
    float S = 0.f;
    #pragma unroll
    for (int k = 0; k < NJT2; k++) S += g_ps[i][k] * expf(g_pm[i][k] - M);
    g_ce[i] = M + logf(S) - g_ref[i];
}

// ---------------- center loss ----------------
__global__ void center_kernel(const float* __restrict__ E, const float* __restrict__ Ctr) {
    int i = blockIdx.x;
    int t = threadIdx.x;
    int lab = g_lab[i];
    const float* e = E   + (size_t)i   * FDIM;
    const float* c = Ctr + (size_t)lab * FDIM;
    float a = 0.f;
    for (int k = t; k < FDIM; k += 128) { float d = e[k] - c[k]; a += d * d; }
    for (int off = 16; off > 0; off >>= 1) a += __shfl_xor_sync(0xffffffff, a, off);
    __shared__ float wsum[4];
    if ((t & 31) == 0) wsum[t >> 5] = a;
    __syncthreads();
    if (t == 0) g_cent[i] = wsum[0] + wsum[1] + wsum[2] + wsum[3];
}

// ---------------- final reduction ----------------
__global__ void final_kernel(float* __restrict__ out) {
    int t = threadIdx.x;
    float l = 0.f;
    for (int i = t; i < BATCH; i += 256) {
        float ap = __uint_as_float(g_ap[i]);
        float an = __uint_as_float(g_an[i]);
        l += fmaxf(ap - an + MARGIN, 0.f) + LAMBDA * g_cent[i] + g_ce[i];
    }
    __shared__ float red[256];
    red[t] = l;
    __syncthreads();
    for (int off = 128; off > 0; off >>= 1) {
        if (t < off) red[t] += red[t + off];
        __syncthreads();
    }
    if (t == 0) out[0] = red[0] / (float)BATCH;
}

// ---------------- launch ----------------
extern "C" void kernel_launch(void* const* d_in, const int* in_sizes, int n_in,
                              void* d_out, int out_size) {
    const float* E    = (const float*)d_in[0];
    const void*  labs = d_in[1];
    const float* Ctr  = (const float*)d_in[2];
    const float* W    = (const float*)d_in[3];
    const float* bvec = (const float*)d_in[4];
    float* out = (float*)d_out;

    detect_kernel<<<1, 256>>>((const long long*)labs);
    prep_kernel<<<BATCH, 128>>>(E, labs);
    triplet_mma_kernel<<<dim3(BATCH / BM, BATCH / BN), 256>>>(E);
    ce_mma_kernel<<<dim3(BATCH / BM, 1024 / BN), 256>>>(E, W, bvec);
    ce_merge_kernel<<<BATCH / 256, 256>>>();
    center_kernel<<<BATCH, 128>>>(E, Ctr);
    final_kernel<<<1, 256>>>(out);
}

// round 8
// speedup vs baseline: 6.2294x; 1.0147x over previous
#include <cuda_runtime.h>
#include <cuda_bf16.h>
#include <math.h>
#include <stdint.h>

#define BATCH 4096
#define FDIM  512
#define NCLS  1000
#define MARGIN 0.3f
#define LAMBDA 0.01f
#define EPSV   1e-12f
#define NJT2  16         // CE partials per row: 8 j-tiles x 2 warp-halves

#define BM 128
#define BN 128
#define BK 32
#define SSTR 36                          // smem row stride (floats), conflict-free frag loads
#define STAGE_FLOATS ((BM + BN) * SSTR)  // 9216
#define STAGE_BYTES  (STAGE_FLOATS * 4)  // 36864
#define DYN_BYTES    (2 * STAGE_BYTES)   // 73728

// ---------------- device scratch ----------------
__device__ float        g_sq[BATCH];
__device__ int          g_lab[BATCH];
__device__ unsigned int g_ap[BATCH];
__device__ unsigned int g_an[BATCH];
__device__ float        g_cent[BATCH];
__device__ float        g_pm[BATCH][NJT2];
__device__ float        g_ps[BATCH][NJT2];
__device__ float        g_ref[BATCH];
__device__ int          g_labmode;

// ---------------- helpers ----------------
__device__ __forceinline__ uint32_t smem_u32(const void* p) {
    uint32_t a;
    asm("{ .reg .u64 t; cvta.to.shared.u64 t, %1; cvt.u32.u64 %0, t; }" : "=r"(a) : "l"(p));
    return a;
}
__device__ __forceinline__ void cp16(uint32_t dst, const void* src) {
    asm volatile("cp.async.cg.shared.global [%0], [%1], 16;" :: "r"(dst), "l"(src));
}
__device__ __forceinline__ void cp_commit() {
    asm volatile("cp.async.commit_group;" ::: "memory");
}
template<int N> __device__ __forceinline__ void cp_wait() {
    asm volatile("cp.async.wait_group %0;" :: "n"(N) : "memory");
}
__device__ __forceinline__ void mma_tf32(float* c, const uint32_t* a, uint32_t b0, uint32_t b1) {
    asm volatile(
        "mma.sync.aligned.m16n8k8.row.col.f32.tf32.tf32.f32 "
        "{%0,%1,%2,%3}, {%4,%5,%6,%7}, {%8,%9}, {%0,%1,%2,%3};"
        : "+f"(c[0]), "+f"(c[1]), "+f"(c[2]), "+f"(c[3])
        : "r"(a[0]), "r"(a[1]), "r"(a[2]), "r"(a[3]), "r"(b0), "r"(b1));
}

// ---------------- label dtype detection ----------------
__global__ void detect_kernel(const long long* __restrict__ lab64) {
    __shared__ int bad;
    if (threadIdx.x == 0) bad = 0;
    __syncthreads();
    int mybad = 0;
    for (int i = threadIdx.x; i < 2048; i += blockDim.x) {
        long long v = lab64[i];
        if (v < 0 || v >= NCLS) mybad = 1;
    }
    if (mybad) atomicOr(&bad, 1);
    __syncthreads();
    if (threadIdx.x == 0) g_labmode = bad ? 1 : 0;
}

// ---------------- fused prep + center: one pass over E ----------------
__global__ void prep_center_kernel(const float* __restrict__ E, const void* __restrict__ labels,
                                   const float* __restrict__ Ctr) {
    int i = blockIdx.x;
    int t = threadIdx.x;    // 128
    __shared__ int slab;
    if (t == 0) {
        int lab;
        if (g_labmode == 0) lab = (int)((const long long*)labels)[i];
        else                lab = ((const int*)labels)[i];
        g_lab[i] = lab;
        slab = lab;
        g_ap[i] = 0u;
        g_an[i] = 0x7f800000u;
    }
    __syncthreads();
    int lab = slab;
    const float* e = E   + (size_t)i   * FDIM;
    const float* c = Ctr + (size_t)lab * FDIM;
    float sq = 0.f, cd = 0.f;
    for (int k = t; k < FDIM; k += 128) {
        float ev = e[k];
        sq += ev * ev;
        float d = ev - c[k];
        cd += d * d;
    }
    for (int off = 16; off > 0; off >>= 1) {
        sq += __shfl_xor_sync(0xffffffff, sq, off);
        cd += __shfl_xor_sync(0xffffffff, cd, off);
    }
    __shared__ float wsq[4], wcd[4];
    if ((t & 31) == 0) { wsq[t >> 5] = sq; wcd[t >> 5] = cd; }
    __syncthreads();
    if (t == 0) {
        g_sq[i]   = wsq[0] + wsq[1] + wsq[2] + wsq[3];
        g_cent[i] = wcd[0] + wcd[1] + wcd[2] + wcd[3];
    }
}

// ---------------- triplet: tf32 mma.sync Gram, cp.async double-buffered ----------------
__global__ __launch_bounds__(256) void triplet_mma_kernel(const float* __restrict__ E) {
    extern __shared__ float dynsm[];
    __shared__ float sQi[BM]; __shared__ int sLi[BM];
    __shared__ float sQj[BN]; __shared__ int sLj[BN];

    int t = threadIdx.x;
    int lane = t & 31, wid = t >> 5;
    int wm = wid >> 1, wn = wid & 1;
    int g = lane >> 2, tg = lane & 3;
    int i0 = blockIdx.x * BM, j0 = blockIdx.y * BN;

    uint32_t sbase = smem_u32(dynsm);
    int r8 = t >> 3, q8 = t & 7;              // row/float4 for cp.async (4 iters of 256)

    if (t < BM)            { sQi[t] = g_sq[i0 + t]; sLi[t] = g_lab[i0 + t]; }
    else if (t < BM + BN)  { int u = t - BM; sQj[u] = g_sq[j0 + u]; sLj[u] = g_lab[j0 + u]; }

    // prologue: chunk 0 -> stage 0
    {
        uint32_t ab = sbase;
        #pragma unroll
        for (int s = 0; s < 4; s++) {
            int r = r8 + s * 32;
            uint32_t off = (uint32_t)(r * SSTR + q8 * 4) * 4;
            cp16(ab + off,                   &E[(size_t)(i0 + r) * FDIM + q8 * 4]);
            cp16(ab + BM * SSTR * 4 + off,   &E[(size_t)(j0 + r) * FDIM + q8 * 4]);
        }
        cp_commit();
    }

    float acc[2][8][4];
    #pragma unroll
    for (int mt = 0; mt < 2; mt++)
        #pragma unroll
        for (int nt = 0; nt < 8; nt++)
            #pragma unroll
            for (int e = 0; e < 4; e++) acc[mt][nt][e] = 0.f;

    const int NCH = FDIM / BK;   // 16
    #pragma unroll 1
    for (int c = 0; c < NCH; c++) {
        if (c + 1 < NCH) {
            uint32_t ab = sbase + ((c + 1) & 1) * STAGE_BYTES;
            int kof = (c + 1) * BK;
            #pragma unroll
            for (int s = 0; s < 4; s++) {
                int r = r8 + s * 32;
                uint32_t off = (uint32_t)(r * SSTR + q8 * 4) * 4;
                cp16(ab + off,                 &E[(size_t)(i0 + r) * FDIM + kof + q8 * 4]);
                cp16(ab + BM * SSTR * 4 + off, &E[(size_t)(j0 + r) * FDIM + kof + q8 * 4]);
            }
            cp_commit();
            cp_wait<1>();
        } else {
            cp_wait<0>();
        }
        __syncthreads();
        const float (*cA)[SSTR] = (const float (*)[SSTR])(dynsm + (c & 1) * STAGE_FLOATS);
        const float (*cB)[SSTR] = (const float (*)[SSTR])(dynsm + (c & 1) * STAGE_FLOATS + BM * SSTR);
        #pragma unroll
        for (int k8 = 0; k8 < 4; k8++) {
            int kc = k8 * 8;
            uint32_t af[2][4];
            #pragma unroll
            for (int mt = 0; mt < 2; mt++) {
                int r = wm * 32 + mt * 16;
                af[mt][0] = __float_as_uint(cA[r + g    ][kc + tg    ]);
                af[mt][1] = __float_as_uint(cA[r + g + 8][kc + tg    ]);
                af[mt][2] = __float_as_uint(cA[r + g    ][kc + tg + 4]);
                af[mt][3] = __float_as_uint(cA[r + g + 8][kc + tg + 4]);
            }
            #pragma unroll
            for (int nt = 0; nt < 8; nt++) {
                int rn = wn * 64 + nt * 8;
                uint32_t b0 = __float_as_uint(cB[rn + g][kc + tg    ]);
                uint32_t b1 = __float_as_uint(cB[rn + g][kc + tg + 4]);
                mma_tf32(acc[0][nt], af[0], b0, b1);
                mma_tf32(acc[1][nt], af[1], b0, b1);
            }
        }
        __syncthreads();   // all warps done with stage (c&1) before chunk c+2 overwrites
    }

    // epilogue: dist + hardest pos/neg
    #pragma unroll
    for (int mt = 0; mt < 2; mt++) {
        #pragma unroll
        for (int half = 0; half < 2; half++) {
            int lr = wm * 32 + mt * 16 + g + half * 8;
            float qi = sQi[lr]; int li = sLi[lr];
            float ap = 0.f, an = INFINITY;
            #pragma unroll
            for (int nt = 0; nt < 8; nt++) {
                #pragma unroll
                for (int e = 0; e < 2; e++) {
                    int lc = wn * 64 + nt * 8 + 2 * tg + e;
                    float d2 = qi + sQj[lc] - 2.f * acc[mt][nt][half * 2 + e];
                    float dist = sqrtf(fmaxf(d2, EPSV));
                    if (sLj[lc] == li) ap = fmaxf(ap, dist);
                    else               an = fminf(an, dist);
                }
            }
            ap = fmaxf(ap, __shfl_xor_sync(0xffffffff, ap, 1));
            ap = fmaxf(ap, __shfl_xor_sync(0xffffffff, ap, 2));
            an = fminf(an, __shfl_xor_sync(0xffffffff, an, 1));
            an = fminf(an, __shfl_xor_sync(0xffffffff, an, 2));
            if (tg == 0) {
                atomicMax(&g_ap[i0 + lr], __float_as_uint(ap));
                atomicMin(&g_an[i0 + lr], __float_as_uint(an));
            }
        }
    }
}

// ---------------- CE: tf32 mma.sync logits, cp.async double-buffered ----------------
__global__ __launch_bounds__(256) void ce_mma_kernel(const float* __restrict__ E,
                                                     const float* __restrict__ W,
                                                     const float* __restrict__ bvec) {
    extern __shared__ float dynsm[];
    __shared__ float sBias[BN];
    __shared__ int   sLab[BM];

    int t = threadIdx.x;
    int lane = t & 31, wid = t >> 5;
    int wm = wid >> 1, wn = wid & 1;
    int g = lane >> 2, tg = lane & 3;
    int i0 = blockIdx.x * BM, j0 = blockIdx.y * BN;
    int jt = blockIdx.y;

    uint32_t sbase = smem_u32(dynsm);
    int r8 = t >> 3, q8 = t & 7;

    if (t < BN)           { int cls = j0 + t; sBias[t] = bvec[cls < NCLS ? cls : NCLS - 1]; }
    else if (t < BN + BM) { sLab[t - BN] = g_lab[i0 + (t - BN)]; }

    {
        uint32_t ab = sbase;
        #pragma unroll
        for (int s = 0; s < 4; s++) {
            int r = r8 + s * 32;
            uint32_t off = (uint32_t)(r * SSTR + q8 * 4) * 4;
            cp16(ab + off, &E[(size_t)(i0 + r) * FDIM + q8 * 4]);
            int wr = j0 + r; if (wr >= NCLS) wr = NCLS - 1;
            cp16(ab + BM * SSTR * 4 + off, &W[(size_t)wr * FDIM + q8 * 4]);
        }
        cp_commit();
    }

    float acc[2][8][4];
    #pragma unroll
    for (int mt = 0; mt < 2; mt++)
        #pragma unroll
        for (int nt = 0; nt < 8; nt++)
            #pragma unroll
            for (int e = 0; e < 4; e++) acc[mt][nt][e] = 0.f;

    const int NCH = FDIM / BK;
    #pragma unroll 1
    for (int c = 0; c < NCH; c++) {
        if (c + 1 < NCH) {
            uint32_t ab = sbase + ((c + 1) & 1) * STAGE_BYTES;
            int kof = (c + 1) * BK;
            #pragma unroll
            for (int s = 0; s < 4; s++) {
                int r = r8 + s * 32;
                uint32_t off = (uint32_t)(r * SSTR + q8 * 4) * 4;
                cp16(ab + off, &E[(size_t)(i0 + r) * FDIM + kof + q8 * 4]);
                int wr = j0 + r; if (wr >= NCLS) wr = NCLS - 1;
                cp16(ab + BM * SSTR * 4 + off, &W[(size_t)wr * FDIM + kof + q8 * 4]);
            }
            cp_commit();
            cp_wait<1>();
        } else {
            cp_wait<0>();
        }
        __syncthreads();
        const float (*cA)[SSTR] = (const float (*)[SSTR])(dynsm + (c & 1) * STAGE_FLOATS);
        const float (*cB)[SSTR] = (const float (*)[SSTR])(dynsm + (c & 1) * STAGE_FLOATS + BM * SSTR);
        #pragma unroll
        for (int k8 = 0; k8 < 4; k8++) {
            int kc = k8 * 8;
            uint32_t af[2][4];
            #pragma unroll
            for (int mt = 0; mt < 2; mt++) {
                int r = wm * 32 + mt * 16;
                af[mt][0] = __float_as_uint(cA[r + g    ][kc + tg    ]);
                af[mt][1] = __float_as_uint(cA[r + g + 8][kc + tg    ]);
                af[mt][2] = __float_as_uint(cA[r + g    ][kc + tg + 4]);
                af[mt][3] = __float_as_uint(cA[r + g + 8][kc + tg + 4]);
            }
            #pragma unroll
            for (int nt = 0; nt < 8; nt++) {
                int rn = wn * 64 + nt * 8;
                uint32_t b0 = __float_as_uint(cB[rn + g][kc + tg    ]);
                uint32_t b1 = __float_as_uint(cB[rn + g][kc + tg + 4]);
                mma_tf32(acc[0][nt], af[0], b0, b1);
                mma_tf32(acc[1][nt], af[1], b0, b1);
            }
        }
        __syncthreads();
    }

    // epilogue: masked bias-add, per-(row, warp-half) partial (max, sumexp)
    #pragma unroll
    for (int mt = 0; mt < 2; mt++) {
        #pragma unroll
        for (int half = 0; half < 2; half++) {
            int lr = wm * 32 + mt * 16 + g + half * 8;
            int irow = i0 + lr;
            int lab  = sLab[lr];
            float v[16];
            float m = -INFINITY;
            #pragma unroll
            for (int nt = 0; nt < 8; nt++) {
                #pragma unroll
                for (int e = 0; e < 2; e++) {
                    int lc  = wn * 64 + nt * 8 + 2 * tg + e;
                    int col = j0 + lc;
                    float x = (col < NCLS) ? (acc[mt][nt][half * 2 + e] + sBias[lc]) : -INFINITY;
                    if (col == lab) g_ref[irow] = x;
                    v[nt * 2 + e] = x;
                    m = fmaxf(m, x);
                }
            }
            m = fmaxf(m, __shfl_xor_sync(0xffffffff, m, 1));
            m = fmaxf(m, __shfl_xor_sync(0xffffffff, m, 2));
            float s = 0.f;
            #pragma unroll
            for (int q = 0; q < 16; q++) s += __expf(v[q] - m);
            s += __shfl_xor_sync(0xffffffff, s, 1);
            s += __shfl_xor_sync(0xffffffff, s, 2);
            if (tg == 0) { g_pm[irow][jt * 2 + wn] = m; g_ps[irow][jt * 2 + wn] = s; }
        }
    }
}

// ---------------- final: CE merge + total loss (deterministic) ----------------
__global__ void final_kernel(float* __restrict__ out) {
    int t = threadIdx.x;   // 256
    float l = 0.f;
    for (int i = t; i < BATCH; i += 256) {
        float M = -INFINITY;
        #pragma unroll
        for (int k = 0; k < NJT2; k++) M = fmaxf(M, g_pm[i][k]);
        float S = 0.f;
        #pragma unroll
        for (int k = 0; k < NJT2; k++) S += g_ps[i][k] * expf(g_pm[i][k] - M);
        float ce = M + logf(S) - g_ref[i];
        float ap = __uint_as_float(g_ap[i]);
        float an = __uint_as_float(g_an[i]);
        l += fmaxf(ap - an + MARGIN, 0.f) + LAMBDA * g_cent[i] + ce;
    }
    __shared__ float red[256];
    red[t] = l;
    __syncthreads();
    for (int off = 128; off > 0; off >>= 1) {
        if (t < off) red[t] += red[t + off];
        __syncthreads();
    }
    if (t == 0) out[0] = red[0] / (float)BATCH;
}

// ---------------- launch ----------------
extern "C" void kernel_launch(void* const* d_in, const int* in_sizes, int n_in,
                              void* d_out, int out_size) {
    const float* E    = (const float*)d_in[0];
    const void*  labs = d_in[1];
    const float* Ctr  = (const float*)d_in[2];
    const float* W    = (const float*)d_in[3];
    const float* bvec = (const float*)d_in[4];
    float* out = (float*)d_out;

    // idempotent; persists from the pre-capture correctness call (return ignored in-capture)
    cudaFuncSetAttribute(triplet_mma_kernel, cudaFuncAttributeMaxDynamicSharedMemorySize, DYN_BYTES);
    cudaFuncSetAttribute(ce_mma_kernel,      cudaFuncAttributeMaxDynamicSharedMemorySize, DYN_BYTES);

    detect_kernel<<<1, 256>>>((const long long*)labs);
    prep_center_kernel<<<BATCH, 128>>>(E, labs, Ctr);
    triplet_mma_kernel<<<dim3(BATCH / BM, BATCH / BN), 256, DYN_BYTES>>>(E);
    ce_mma_kernel<<<dim3(BATCH / BM, 1024 / BN), 256, DYN_BYTES>>>(E, W, bvec);
    final_kernel<<<1, 256>>>(out);
}

// round 9
// speedup vs baseline: 6.2343x; 1.0008x over previous
#include <cuda_runtime.h>
#include <cuda_bf16.h>
#include <math.h>
#include <stdint.h>

#define BATCH 4096
#define FDIM  512
#define NCLS  1000
#define MARGIN 0.3f
#define LAMBDA 0.01f
#define EPSV   1e-12f
#define NJT2  16         // CE partials per row: 8 j-tiles x 2 warp-halves

#define BM 128
#define BN 128
#define BK 16
#define SSTR 20                          // smem row stride (floats); 16B-aligned rows, conflict-free
#define STAGES 4
#define NCH (FDIM / BK)                  // 32
#define STAGE_FLOATS ((BM + BN) * SSTR)  // 5120
#define STAGE_BYTES  (STAGE_FLOATS * 4)  // 20480
#define DYN_BYTES    (STAGES * STAGE_BYTES)  // 81920

#define NTILE (BATCH / BM)               // 32
#define NTRI  (NTILE * (NTILE + 1) / 2)  // 528

// ---------------- device scratch ----------------
__device__ float        g_sq[BATCH];
__device__ int          g_lab[BATCH];
__device__ unsigned int g_ap[BATCH];
__device__ unsigned int g_an[BATCH];
__device__ float        g_cent[BATCH];
__device__ float        g_pm[BATCH][NJT2];
__device__ float        g_ps[BATCH][NJT2];
__device__ float        g_ref[BATCH];
__device__ int          g_labmode;

// ---------------- helpers ----------------
__device__ __forceinline__ uint32_t smem_u32(const void* p) {
    uint32_t a;
    asm("{ .reg .u64 t; cvta.to.shared.u64 t, %1; cvt.u32.u64 %0, t; }" : "=r"(a) : "l"(p));
    return a;
}
__device__ __forceinline__ void cp16(uint32_t dst, const void* src) {
    asm volatile("cp.async.cg.shared.global [%0], [%1], 16;" :: "r"(dst), "l"(src));
}
__device__ __forceinline__ void cp_commit() {
    asm volatile("cp.async.commit_group;" ::: "memory");
}
template<int N> __device__ __forceinline__ void cp_wait() {
    asm volatile("cp.async.wait_group %0;" :: "n"(N) : "memory");
}
__device__ __forceinline__ void mma_tf32(float* c, const uint32_t* a, uint32_t b0, uint32_t b1) {
    asm volatile(
        "mma.sync.aligned.m16n8k8.row.col.f32.tf32.tf32.f32 "
        "{%0,%1,%2,%3}, {%4,%5,%6,%7}, {%8,%9}, {%0,%1,%2,%3};"
        : "+f"(c[0]), "+f"(c[1]), "+f"(c[2]), "+f"(c[3])
        : "r"(a[0]), "r"(a[1]), "r"(a[2]), "r"(a[3]), "r"(b0), "r"(b1));
}

// ---------------- label dtype detection ----------------
__global__ void detect_kernel(const long long* __restrict__ lab64) {
    __shared__ int bad;
    if (threadIdx.x == 0) bad = 0;
    __syncthreads();
    int mybad = 0;
    for (int i = threadIdx.x; i < 2048; i += blockDim.x) {
        long long v = lab64[i];
        if (v < 0 || v >= NCLS) mybad = 1;
    }
    if (mybad) atomicOr(&bad, 1);
    __syncthreads();
    if (threadIdx.x == 0) g_labmode = bad ? 1 : 0;
}

// ---------------- fused prep + center: one pass over E ----------------
__global__ void prep_center_kernel(const float* __restrict__ E, const void* __restrict__ labels,
                                   const float* __restrict__ Ctr) {
    int i = blockIdx.x;
    int t = threadIdx.x;    // 128
    __shared__ int slab;
    if (t == 0) {
        int lab;
        if (g_labmode == 0) lab = (int)((const long long*)labels)[i];
        else                lab = ((const int*)labels)[i];
        g_lab[i] = lab;
        slab = lab;
        g_ap[i] = 0u;
        g_an[i] = 0x7f800000u;
    }
    __syncthreads();
    int lab = slab;
    const float* e = E   + (size_t)i   * FDIM;
    const float* c = Ctr + (size_t)lab * FDIM;
    float sq = 0.f, cd = 0.f;
    for (int k = t; k < FDIM; k += 128) {
        float ev = e[k];
        sq += ev * ev;
        float d = ev - c[k];
        cd += d * d;
    }
    for (int off = 16; off > 0; off >>= 1) {
        sq += __shfl_xor_sync(0xffffffff, sq, off);
        cd += __shfl_xor_sync(0xffffffff, cd, off);
    }
    __shared__ float wsq[4], wcd[4];
    if ((t & 31) == 0) { wsq[t >> 5] = sq; wcd[t >> 5] = cd; }
    __syncthreads();
    if (t == 0) {
        g_sq[i]   = wsq[0] + wsq[1] + wsq[2] + wsq[3];
        g_cent[i] = wcd[0] + wcd[1] + wcd[2] + wcd[3];
    }
}

// ---------------- triplet: symmetric tf32 Gram, 4-stage pipeline, dual epilogue ----------------
__global__ __launch_bounds__(256, 2) void triplet_mma_kernel(const float* __restrict__ E) {
    extern __shared__ float dynsm[];
    __shared__ float sQi[BM]; __shared__ int sLi[BM];
    __shared__ float sQj[BN]; __shared__ int sLj[BN];

    // triangular decode: block -> (bi, bj) with bj >= bi
    int rem = blockIdx.x, bi = 0;
    #pragma unroll 1
    for (;;) { int len = NTILE - bi; if (rem < len) break; rem -= len; bi++; }
    int bj = bi + rem;
    bool diag = (bi == bj);

    int t = threadIdx.x;
    int lane = t & 31, wid = t >> 5;
    int wm = wid >> 1, wn = wid & 1;
    int g = lane >> 2, tg = lane & 3;
    int i0 = bi * BM, j0 = bj * BN;

    uint32_t sbase = smem_u32(dynsm);
    int r4 = t >> 1, q4 = t & 1;    // 256 threads -> per matrix: 128 rows x 4 float4; 2 iters

    if (t < BM)            { sQi[t] = g_sq[i0 + t]; sLi[t] = g_lab[i0 + t]; }
    else if (t < BM + BN)  { int u = t - BM; sQj[u] = g_sq[j0 + u]; sLj[u] = g_lab[j0 + u]; }

    // prologue: chunks 0..2 -> stages 0..2
    #pragma unroll
    for (int p = 0; p < STAGES - 1; p++) {
        uint32_t ab = sbase + p * STAGE_BYTES;
        int kof = p * BK;
        #pragma unroll
        for (int s = 0; s < 2; s++) {
            int r = r4, q = q4 + s * 2;
            uint32_t off = (uint32_t)(r * SSTR + q * 4) * 4;
            cp16(ab + off,                 &E[(size_t)(i0 + r) * FDIM + kof + q * 4]);
            cp16(ab + BM * SSTR * 4 + off, &E[(size_t)(j0 + r) * FDIM + kof + q * 4]);
        }
        cp_commit();
    }

    float acc[2][8][4];
    #pragma unroll
    for (int mt = 0; mt < 2; mt++)
        #pragma unroll
        for (int nt = 0; nt < 8; nt++)
            #pragma unroll
            for (int e = 0; e < 4; e++) acc[mt][nt][e] = 0.f;

    #pragma unroll 1
    for (int c = 0; c < NCH; c++) {
        cp_wait<STAGES - 2>();     // chunk c resident
        __syncthreads();           // all warps done with stage (c-1)%STAGES
        if (c + STAGES - 1 < NCH) {
            uint32_t ab = sbase + ((c + STAGES - 1) % STAGES) * STAGE_BYTES;
            int kof = (c + STAGES - 1) * BK;
            #pragma unroll
            for (int s = 0; s < 2; s++) {
                int r = r4, q = q4 + s * 2;
                uint32_t off = (uint32_t)(r * SSTR + q * 4) * 4;
                cp16(ab + off,                 &E[(size_t)(i0 + r) * FDIM + kof + q * 4]);
                cp16(ab + BM * SSTR * 4 + off, &E[(size_t)(j0 + r) * FDIM + kof + q * 4]);
            }
        }
        cp_commit();               // empty group in tail keeps wait<2> uniform
        const float (*cA)[SSTR] = (const float (*)[SSTR])(dynsm + (c % STAGES) * STAGE_FLOATS);
        const float (*cB)[SSTR] = (const float (*)[SSTR])(dynsm + (c % STAGES) * STAGE_FLOATS + BM * SSTR);
        #pragma unroll
        for (int k8 = 0; k8 < 2; k8++) {
            int kc = k8 * 8;
            uint32_t af[2][4];
            #pragma unroll
            for (int mt = 0; mt < 2; mt++) {
                int r = wm * 32 + mt * 16;
                af[mt][0] = __float_as_uint(cA[r + g    ][kc + tg    ]);
                af[mt][1] = __float_as_uint(cA[r + g + 8][kc + tg    ]);
                af[mt][2] = __float_as_uint(cA[r + g    ][kc + tg + 4]);
                af[mt][3] = __float_as_uint(cA[r + g + 8][kc + tg + 4]);
            }
            #pragma unroll
            for (int nt = 0; nt < 8; nt++) {
                int rn = wn * 64 + nt * 8;
                uint32_t b0 = __float_as_uint(cB[rn + g][kc + tg    ]);
                uint32_t b1 = __float_as_uint(cB[rn + g][kc + tg + 4]);
                mma_tf32(acc[0][nt], af[0], b0, b1);
                mma_tf32(acc[1][nt], af[1], b0, b1);
            }
        }
    }

    // ---- dual-sided epilogue ----
    float rap[4], ran[4];
    float cap[16], can[16];
    #pragma unroll
    for (int s4 = 0; s4 < 4; s4++) { rap[s4] = 0.f; ran[s4] = INFINITY; }
    #pragma unroll
    for (int cs = 0; cs < 16; cs++) { cap[cs] = 0.f; can[cs] = INFINITY; }

    #pragma unroll
    for (int mt = 0; mt < 2; mt++) {
        #pragma unroll
        for (int half = 0; half < 2; half++) {
            int lr = wm * 32 + mt * 16 + g + half * 8;
            float qi = sQi[lr]; int li = sLi[lr];
            int slot = mt * 2 + half;
            #pragma unroll
            for (int nt = 0; nt < 8; nt++) {
                #pragma unroll
                for (int e = 0; e < 2; e++) {
                    int lc = wn * 64 + nt * 8 + 2 * tg + e;
                    float d2 = qi + sQj[lc] - 2.f * acc[mt][nt][half * 2 + e];
                    float dist = sqrtf(fmaxf(d2, EPSV));
                    bool same = (sLj[lc] == li);
                    if (same) rap[slot] = fmaxf(rap[slot], dist);
                    else      ran[slot] = fminf(ran[slot], dist);
                    if (!diag) {
                        int cs = nt * 2 + e;
                        if (same) cap[cs] = fmaxf(cap[cs], dist);
                        else      can[cs] = fminf(can[cs], dist);
                    }
                }
            }
        }
    }

    // rows: reduce over tg (lane bits 0..1)
    #pragma unroll
    for (int s4 = 0; s4 < 4; s4++) {
        rap[s4] = fmaxf(rap[s4], __shfl_xor_sync(0xffffffff, rap[s4], 1));
        rap[s4] = fmaxf(rap[s4], __shfl_xor_sync(0xffffffff, rap[s4], 2));
        ran[s4] = fminf(ran[s4], __shfl_xor_sync(0xffffffff, ran[s4], 1));
        ran[s4] = fminf(ran[s4], __shfl_xor_sync(0xffffffff, ran[s4], 2));
    }
    if (tg == 0) {
        #pragma unroll
        for (int s4 = 0; s4 < 4; s4++) {
            int lr = wm * 32 + (s4 >> 1) * 16 + g + (s4 & 1) * 8;
            atomicMax(&g_ap[i0 + lr], __float_as_uint(rap[s4]));
            atomicMin(&g_an[i0 + lr], __float_as_uint(ran[s4]));
        }
    }
    // columns: reduce over g (lane bits 2..4)
    if (!diag) {
        #pragma unroll
        for (int cs = 0; cs < 16; cs++) {
            cap[cs] = fmaxf(cap[cs], __shfl_xor_sync(0xffffffff, cap[cs], 4));
            cap[cs] = fmaxf(cap[cs], __shfl_xor_sync(0xffffffff, cap[cs], 8));
            cap[cs] = fmaxf(cap[cs], __shfl_xor_sync(0xffffffff, cap[cs], 16));
            can[cs] = fminf(can[cs], __shfl_xor_sync(0xffffffff, can[cs], 4));
            can[cs] = fminf(can[cs], __shfl_xor_sync(0xffffffff, can[cs], 8));
            can[cs] = fminf(can[cs], __shfl_xor_sync(0xffffffff, can[cs], 16));
        }
        if (lane < 4) {   // g == 0; tg == lane
            #pragma unroll
            for (int cs = 0; cs < 16; cs++) {
                int col = j0 + wn * 64 + (cs >> 1) * 8 + 2 * lane + (cs & 1);
                atomicMax(&g_ap[col], __float_as_uint(cap[cs]));
                atomicMin(&g_an[col], __float_as_uint(can[cs]));
            }
        }
    }
}

// ---------------- CE: tf32 logits, 4-stage pipeline ----------------
__global__ __launch_bounds__(256, 2) void ce_mma_kernel(const float* __restrict__ E,
                                                        const float* __restrict__ W,
                                                        const float* __restrict__ bvec) {
    extern __shared__ float dynsm[];
    __shared__ float sBias[BN];
    __shared__ int   sLab[BM];

    int t = threadIdx.x;
    int lane = t & 31, wid = t >> 5;
    int wm = wid >> 1, wn = wid & 1;
    int g = lane >> 2, tg = lane & 3;
    int i0 = blockIdx.x * BM, j0 = blockIdx.y * BN;
    int jt = blockIdx.y;

    uint32_t sbase = smem_u32(dynsm);
    int r4 = t >> 1, q4 = t & 1;

    if (t < BN)           { int cls = j0 + t; sBias[t] = bvec[cls < NCLS ? cls : NCLS - 1]; }
    else if (t < BN + BM) { sLab[t - BN] = g_lab[i0 + (t - BN)]; }

    int wr_clamped = j0 + r4; if (wr_clamped >= NCLS) wr_clamped = NCLS - 1;

    #pragma unroll
    for (int p = 0; p < STAGES - 1; p++) {
        uint32_t ab = sbase + p * STAGE_BYTES;
        int kof = p * BK;
        #pragma unroll
        for (int s = 0; s < 2; s++) {
            int r = r4, q = q4 + s * 2;
            uint32_t off = (uint32_t)(r * SSTR + q * 4) * 4;
            cp16(ab + off,                 &E[(size_t)(i0 + r) * FDIM + kof + q * 4]);
            cp16(ab + BM * SSTR * 4 + off, &W[(size_t)wr_clamped * FDIM + kof + q * 4]);
        }
        cp_commit();
    }

    float acc[2][8][4];
    #pragma unroll
    for (int mt = 0; mt < 2; mt++)
        #pragma unroll
        for (int nt = 0; nt < 8; nt++)
            #pragma unroll
            for (int e = 0; e < 4; e++) acc[mt][nt][e] = 0.f;

    #pragma unroll 1
    for (int c = 0; c < NCH; c++) {
        cp_wait<STAGES - 2>();
        __syncthreads();
        if (c + STAGES - 1 < NCH) {
            uint32_t ab = sbase + ((c + STAGES - 1) % STAGES) * STAGE_BYTES;
            int kof = (c + STAGES - 1) * BK;
            #pragma unroll
            for (int s = 0; s < 2; s++) {
                int r = r4, q = q4 + s * 2;
                uint32_t off = (uint32_t)(r * SSTR + q * 4) * 4;
                cp16(ab + off,                 &E[(size_t)(i0 + r) * FDIM + kof + q * 4]);
                cp16(ab + BM * SSTR * 4 + off, &W[(size_t)wr_clamped * FDIM + kof + q * 4]);
            }
        }
        cp_commit();
        const float (*cA)[SSTR] = (const float (*)[SSTR])(dynsm + (c % STAGES) * STAGE_FLOATS);
        const float (*cB)[SSTR] = (const float (*)[SSTR])(dynsm + (c % STAGES) * STAGE_FLOATS + BM * SSTR);
        #pragma unroll
        for (int k8 = 0; k8 < 2; k8++) {
            int kc = k8 * 8;
            uint32_t af[2][4];
            #pragma unroll
            for (int mt = 0; mt < 2; mt++) {
                int r = wm * 32 + mt * 16;
                af[mt][0] = __float_as_uint(cA[r + g    ][kc + tg    ]);
                af[mt][1] = __float_as_uint(cA[r + g + 8][kc + tg    ]);
                af[mt][2] = __float_as_uint(cA[r + g    ][kc + tg + 4]);
                af[mt][3] = __float_as_uint(cA[r + g + 8][kc + tg + 4]);
            }
            #pragma unroll
            for (int nt = 0; nt < 8; nt++) {
                int rn = wn * 64 + nt * 8;
                uint32_t b0 = __float_as_uint(cB[rn + g][kc + tg    ]);
                uint32_t b1 = __float_as_uint(cB[rn + g][kc + tg + 4]);
                mma_tf32(acc[0][nt], af[0], b0, b1);
                mma_tf32(acc[1][nt], af[1], b0, b1);
            }
        }
    }

    // epilogue: masked bias-add, per-(row, warp-half) partial (max, sumexp)
    #pragma unroll
    for (int mt = 0; mt < 2; mt++) {
        #pragma unroll
        for (int half = 0; half < 2; half++) {
            int lr = wm * 32 + mt * 16 + g + half * 8;
            int irow = i0 + lr;
            int lab  = sLab[lr];
            float v[16];
            float m = -INFINITY;
            #pragma unroll
            for (int nt = 0; nt < 8; nt++) {
                #pragma unroll
                for (int e = 0; e < 2; e++) {
                    int lc  = wn * 64 + nt * 8 + 2 * tg + e;
                    int col = j0 + lc;
                    float x = (col < NCLS) ? (acc[mt][nt][half * 2 + e] + sBias[lc]) : -INFINITY;
                    if (col == lab) g_ref[irow] = x;
                    v[nt * 2 + e] = x;
                    m = fmaxf(m, x);
                }
            }
            m = fmaxf(m, __shfl_xor_sync(0xffffffff, m, 1));
            m = fmaxf(m, __shfl_xor_sync(0xffffffff, m, 2));
            float s = 0.f;
            #pragma unroll
            for (int q = 0; q < 16; q++) s += __expf(v[q] - m);
            s += __shfl_xor_sync(0xffffffff, s, 1);
            s += __shfl_xor_sync(0xffffffff, s, 2);
            if (tg == 0) { g_pm[irow][jt * 2 + wn] = m; g_ps[irow][jt * 2 + wn] = s; }
        }
    }
}

// ---------------- final: CE merge + total loss (deterministic) ----------------
__global__ void final_kernel(float* __restrict__ out) {
    int t = threadIdx.x;   // 256
    float l = 0.f;
    for (int i = t; i < BATCH; i += 256) {
        float M = -INFINITY;
        #pragma unroll
        for (int k = 0; k < NJT2; k++) M = fmaxf(M, g_pm[i][k]);
        float S = 0.f;
        #pragma unroll
        for (int k = 0; k < NJT2; k++) S += g_ps[i][k] * expf(g_pm[i][k] - M);
        float ce = M + logf(S) - g_ref[i];
        float ap = __uint_as_float(g_ap[i]);
        float an = __uint_as_float(g_an[i]);
        l += fmaxf(ap - an + MARGIN, 0.f) + LAMBDA * g_cent[i] + ce;
    }
    __shared__ float red[256];
    red[t] = l;
    __syncthreads();
    for (int off = 128; off > 0; off >>= 1) {
        if (t < off) red[t] += red[t + off];
        __syncthreads();
    }
    if (t == 0) out[0] = red[0] / (float)BATCH;
}

// ---------------- launch ----------------
extern "C" void kernel_launch(void* const* d_in, const int* in_sizes, int n_in,
                              void* d_out, int out_size) {
    const float* E    = (const float*)d_in[0];
    const void*  labs = d_in[1];
    const float* Ctr  = (const float*)d_in[2];
    const float* W    = (const float*)d_in[3];
    const float* bvec = (const float*)d_in[4];
    float* out = (float*)d_out;

    // idempotent; persists from the pre-capture correctness call (return ignored in-capture)
    cudaFuncSetAttribute(triplet_mma_kernel, cudaFuncAttributeMaxDynamicSharedMemorySize, DYN_BYTES);
    cudaFuncSetAttribute(ce_mma_kernel,      cudaFuncAttributeMaxDynamicSharedMemorySize, DYN_BYTES);

    detect_kernel<<<1, 256>>>((const long long*)labs);
    prep_center_kernel<<<BATCH, 128>>>(E, labs, Ctr);
    triplet_mma_kernel<<<NTRI, 256, DYN_BYTES>>>(E);
    ce_mma_kernel<<<dim3(BATCH / BM, 1024 / BN), 256, DYN_BYTES>>>(E, W, bvec);
    final_kernel<<<1, 256>>>(out);
}

// round 11
// speedup vs baseline: 7.9665x; 1.2778x over previous
#include <cuda_runtime.h>
#include <cuda_bf16.h>
#include <math.h>
#include <stdint.h>

#define BATCH 4096
#define FDIM  512
#define NCLS  1000
#define MARGIN 0.3f
#define LAMBDA 0.01f
#define EPSV   1e-12f
#define NJT2  16         // CE partials per row: 8 j-tiles x 2 warp-halves

#define BM 128
#define BN 128
#define BK 32
#define SSTR 36                          // smem row stride (floats), conflict-free frag loads
#define STAGE_FLOATS ((BM + BN) * SSTR)  // 9216
#define STAGE_BYTES  (STAGE_FLOATS * 4)  // 36864
#define DYN_BYTES    (2 * STAGE_BYTES)   // 73728

#define NTILE (BATCH / BM)               // 32
#define NTRI  (NTILE * (NTILE + 1) / 2)  // 528

// ---------------- device scratch ----------------
__device__ float        g_sq[BATCH];
__device__ int          g_lab[BATCH];
__device__ unsigned int g_ap[BATCH];
__device__ unsigned int g_an[BATCH];
__device__ float        g_cent[BATCH];
__device__ float        g_pm[BATCH][NJT2];
__device__ float        g_ps[BATCH][NJT2];
__device__ float        g_ref[BATCH];
__device__ int          g_labmode;

// ---------------- helpers ----------------
__device__ __forceinline__ uint32_t smem_u32(const void* p) {
    uint32_t a;
    asm("{ .reg .u64 t; cvta.to.shared.u64 t, %1; cvt.u32.u64 %0, t; }" : "=r"(a) : "l"(p));
    return a;
}
__device__ __forceinline__ void cp16(uint32_t dst, const void* src) {
    asm volatile("cp.async.cg.shared.global [%0], [%1], 16;" :: "r"(dst), "l"(src));
}
__device__ __forceinline__ void cp_commit() {
    asm volatile("cp.async.commit_group;" ::: "memory");
}
template<int N> __device__ __forceinline__ void cp_wait() {
    asm volatile("cp.async.wait_group %0;" :: "n"(N) : "memory");
}
__device__ __forceinline__ void mma_tf32(float* c, const uint32_t* a, uint32_t b0, uint32_t b1) {
    asm volatile(
        "mma.sync.aligned.m16n8k8.row.col.f32.tf32.tf32.f32 "
        "{%0,%1,%2,%3}, {%4,%5,%6,%7}, {%8,%9}, {%0,%1,%2,%3};"
        : "+f"(c[0]), "+f"(c[1]), "+f"(c[2]), "+f"(c[3])
        : "r"(a[0]), "r"(a[1]), "r"(a[2]), "r"(a[3]), "r"(b0), "r"(b1));
}

// ---------------- label dtype detection ----------------
__global__ void detect_kernel(const long long* __restrict__ lab64) {
    __shared__ int bad;
    if (threadIdx.x == 0) bad = 0;
    __syncthreads();
    int mybad = 0;
    for (int i = threadIdx.x; i < 2048; i += blockDim.x) {
        long long v = lab64[i];
        if (v < 0 || v >= NCLS) mybad = 1;
    }
    if (mybad) atomicOr(&bad, 1);
    __syncthreads();
    if (threadIdx.x == 0) g_labmode = bad ? 1 : 0;
}

// ---------------- fused prep + center: one pass over E ----------------
__global__ void prep_center_kernel(const float* __restrict__ E, const void* __restrict__ labels,
                                   const float* __restrict__ Ctr) {
    int i = blockIdx.x;
    int t = threadIdx.x;    // 128
    __shared__ int slab;
    if (t == 0) {
        int lab;
        if (g_labmode == 0) lab = (int)((const long long*)labels)[i];
        else                lab = ((const int*)labels)[i];
        g_lab[i] = lab;
        slab = lab;
        g_ap[i] = 0u;
        g_an[i] = 0x7f800000u;
    }
    __syncthreads();
    int lab = slab;
    const float* e = E   + (size_t)i   * FDIM;
    const float* c = Ctr + (size_t)lab * FDIM;
    float sq = 0.f, cd = 0.f;
    for (int k = t; k < FDIM; k += 128) {
        float ev = e[k];
        sq += ev * ev;
        float d = ev - c[k];
        cd += d * d;
    }
    for (int off = 16; off > 0; off >>= 1) {
        sq += __shfl_xor_sync(0xffffffff, sq, off);
        cd += __shfl_xor_sync(0xffffffff, cd, off);
    }
    __shared__ float wsq[4], wcd[4];
    if ((t & 31) == 0) { wsq[t >> 5] = sq; wcd[t >> 5] = cd; }
    __syncthreads();
    if (t == 0) {
        g_sq[i]   = wsq[0] + wsq[1] + wsq[2] + wsq[3];
        g_cent[i] = wcd[0] + wcd[1] + wcd[2] + wcd[3];
    }
}

// ---------------- triplet: symmetric tf32 Gram (R8 pipeline), dual epilogue ----------------
__global__ __launch_bounds__(256, 2) void triplet_mma_kernel(const float* __restrict__ E) {
    extern __shared__ float dynsm[];
    __shared__ float sQi[BM]; __shared__ int sLi[BM];
    __shared__ float sQj[BN]; __shared__ int sLj[BN];

    // triangular decode: block -> (bi, bj) with bj >= bi
    int rem = blockIdx.x, bi = 0;
    #pragma unroll 1
    for (;;) { int len = NTILE - bi; if (rem < len) break; rem -= len; bi++; }
    int bj = bi + rem;
    bool diag = (bi == bj);

    int t = threadIdx.x;
    int lane = t & 31, wid = t >> 5;
    int wm = wid >> 1, wn = wid & 1;
    int g = lane >> 2, tg = lane & 3;
    int i0 = bi * BM, j0 = bj * BN;

    uint32_t sbase = smem_u32(dynsm);
    int r8 = t >> 3, q8 = t & 7;              // row/float4 for cp.async (4 iters of 256)

    if (t < BM)            { sQi[t] = g_sq[i0 + t]; sLi[t] = g_lab[i0 + t]; }
    else if (t < BM + BN)  { int u = t - BM; sQj[u] = g_sq[j0 + u]; sLj[u] = g_lab[j0 + u]; }

    // prologue: chunk 0 -> stage 0
    {
        uint32_t ab = sbase;
        #pragma unroll
        for (int s = 0; s < 4; s++) {
            int r = r8 + s * 32;
            uint32_t off = (uint32_t)(r * SSTR + q8 * 4) * 4;
            cp16(ab + off,                   &E[(size_t)(i0 + r) * FDIM + q8 * 4]);
            cp16(ab + BM * SSTR * 4 + off,   &E[(size_t)(j0 + r) * FDIM + q8 * 4]);
        }
        cp_commit();
    }

    float acc[2][8][4];
    #pragma unroll
    for (int mt = 0; mt < 2; mt++)
        #pragma unroll
        for (int nt = 0; nt < 8; nt++)
            #pragma unroll
            for (int e = 0; e < 4; e++) acc[mt][nt][e] = 0.f;

    const int NCH = FDIM / BK;   // 16
    #pragma unroll 1
    for (int c = 0; c < NCH; c++) {
        if (c + 1 < NCH) {
            uint32_t ab = sbase + ((c + 1) & 1) * STAGE_BYTES;
            int kof = (c + 1) * BK;
            #pragma unroll
            for (int s = 0; s < 4; s++) {
                int r = r8 + s * 32;
                uint32_t off = (uint32_t)(r * SSTR + q8 * 4) * 4;
                cp16(ab + off,                 &E[(size_t)(i0 + r) * FDIM + kof + q8 * 4]);
                cp16(ab + BM * SSTR * 4 + off, &E[(size_t)(j0 + r) * FDIM + kof + q8 * 4]);
            }
            cp_commit();
            cp_wait<1>();
        } else {
            cp_wait<0>();
        }
        __syncthreads();
        const float (*cA)[SSTR] = (const float (*)[SSTR])(dynsm + (c & 1) * STAGE_FLOATS);
        const float (*cB)[SSTR] = (const float (*)[SSTR])(dynsm + (c & 1) * STAGE_FLOATS + BM * SSTR);
        #pragma unroll
        for (int k8 = 0; k8 < 4; k8++) {
            int kc = k8 * 8;
            uint32_t af[2][4];
            #pragma unroll
            for (int mt = 0; mt < 2; mt++) {
                int r = wm * 32 + mt * 16;
                af[mt][0] = __float_as_uint(cA[r + g    ][kc + tg    ]);
                af[mt][1] = __float_as_uint(cA[r + g + 8][kc + tg    ]);
                af[mt][2] = __float_as_uint(cA[r + g    ][kc + tg + 4]);
                af[mt][3] = __float_as_uint(cA[r + g + 8][kc + tg + 4]);
            }
            #pragma unroll
            for (int nt = 0; nt < 8; nt++) {
                int rn = wn * 64 + nt * 8;
                uint32_t b0 = __float_as_uint(cB[rn + g][kc + tg    ]);
                uint32_t b1 = __float_as_uint(cB[rn + g][kc + tg + 4]);
                mma_tf32(acc[0][nt], af[0], b0, b1);
                mma_tf32(acc[1][nt], af[1], b0, b1);
            }
        }
        __syncthreads();   // all warps done with stage (c&1) before chunk c+2 overwrites
    }

    // ---- dual-sided epilogue ----
    float rap[4], ran[4];
    float cap[16], can[16];
    #pragma unroll
    for (int s4 = 0; s4 < 4; s4++) { rap[s4] = 0.f; ran[s4] = INFINITY; }
    #pragma unroll
    for (int cs = 0; cs < 16; cs++) { cap[cs] = 0.f; can[cs] = INFINITY; }

    #pragma unroll
    for (int mt = 0; mt < 2; mt++) {
        #pragma unroll
        for (int half = 0; half < 2; half++) {
            int lr = wm * 32 + mt * 16 + g + half * 8;
            float qi = sQi[lr]; int li = sLi[lr];
            int slot = mt * 2 + half;
            #pragma unroll
            for (int nt = 0; nt < 8; nt++) {
                #pragma unroll
                for (int e = 0; e < 2; e++) {
                    int lc = wn * 64 + nt * 8 + 2 * tg + e;
                    float d2 = qi + sQj[lc] - 2.f * acc[mt][nt][half * 2 + e];
                    float dist = sqrtf(fmaxf(d2, EPSV));
                    bool same = (sLj[lc] == li);
                    if (same) rap[slot] = fmaxf(rap[slot], dist);
                    else      ran[slot] = fminf(ran[slot], dist);
                    if (!diag) {
                        int cs = nt * 2 + e;
                        if (same) cap[cs] = fmaxf(cap[cs], dist);
                        else      can[cs] = fminf(can[cs], dist);
                    }
                }
            }
        }
    }

    // rows: reduce over tg (lane bits 0..1)
    #pragma unroll
    for (int s4 = 0; s4 < 4; s4++) {
        rap[s4] = fmaxf(rap[s4], __shfl_xor_sync(0xffffffff, rap[s4], 1));
        rap[s4] = fmaxf(rap[s4], __shfl_xor_sync(0xffffffff, rap[s4], 2));
        ran[s4] = fminf(ran[s4], __shfl_xor_sync(0xffffffff, ran[s4], 1));
        ran[s4] = fminf(ran[s4], __shfl_xor_sync(0xffffffff, ran[s4], 2));
    }
    if (tg == 0) {
        #pragma unroll
        for (int s4 = 0; s4 < 4; s4++) {
            int lr = wm * 32 + (s4 >> 1) * 16 + g + (s4 & 1) * 8;
            atomicMax(&g_ap[i0 + lr], __float_as_uint(rap[s4]));
            atomicMin(&g_an[i0 + lr], __float_as_uint(ran[s4]));
        }
    }
    // columns: reduce over g (lane bits 2..4)
    if (!diag) {
        #pragma unroll
        for (int cs = 0; cs < 16; cs++) {
            cap[cs] = fmaxf(cap[cs], __shfl_xor_sync(0xffffffff, cap[cs], 4));
            cap[cs] = fmaxf(cap[cs], __shfl_xor_sync(0xffffffff, cap[cs], 8));
            cap[cs] = fmaxf(cap[cs], __shfl_xor_sync(0xffffffff, cap[cs], 16));
            can[cs] = fminf(can[cs], __shfl_xor_sync(0xffffffff, can[cs], 4));
            can[cs] = fminf(can[cs], __shfl_xor_sync(0xffffffff, can[cs], 8));
            can[cs] = fminf(can[cs], __shfl_xor_sync(0xffffffff, can[cs], 16));
        }
        if (lane < 4) {   // g == 0; tg == lane
            #pragma unroll
            for (int cs = 0; cs < 16; cs++) {
                int col = j0 + wn * 64 + (cs >> 1) * 8 + 2 * lane + (cs & 1);
                atomicMax(&g_ap[col], __float_as_uint(cap[cs]));
                atomicMin(&g_an[col], __float_as_uint(can[cs]));
            }
        }
    }
}

// ---------------- CE: tf32 logits, R8 pipeline (BK=32, 2-stage) ----------------
__global__ __launch_bounds__(256, 2) void ce_mma_kernel(const float* __restrict__ E,
                                                        const float* __restrict__ W,
                                                        const float* __restrict__ bvec) {
    extern __shared__ float dynsm[];
    __shared__ float sBias[BN];
    __shared__ int   sLab[BM];

    int t = threadIdx.x;
    int lane = t & 31, wid = t >> 5;
    int wm = wid >> 1, wn = wid & 1;
    int g = lane >> 2, tg = lane & 3;
    int i0 = blockIdx.x * BM, j0 = blockIdx.y * BN;
    int jt = blockIdx.y;

    uint32_t sbase = smem_u32(dynsm);
    int r8 = t >> 3, q8 = t & 7;

    if (t < BN)           { int cls = j0 + t; sBias[t] = bvec[cls < NCLS ? cls : NCLS - 1]; }
    else if (t < BN + BM) { sLab[t - BN] = g_lab[i0 + (t - BN)]; }

    {
        uint32_t ab = sbase;
        #pragma unroll
        for (int s = 0; s < 4; s++) {
            int r = r8 + s * 32;
            uint32_t off = (uint32_t)(r * SSTR + q8 * 4) * 4;
            cp16(ab + off, &E[(size_t)(i0 + r) * FDIM + q8 * 4]);
            int wr = j0 + r; if (wr >= NCLS) wr = NCLS - 1;
            cp16(ab + BM * SSTR * 4 + off, &W[(size_t)wr * FDIM + q8 * 4]);
        }
        cp_commit();
    }

    float acc[2][8][4];
    #pragma unroll
    for (int mt = 0; mt < 2; mt++)
        #pragma unroll
        for (int nt = 0; nt < 8; nt++)
            #pragma unroll
            for (int e = 0; e < 4; e++) acc[mt][nt][e] = 0.f;

    const int NCH = FDIM / BK;
    #pragma unroll 1
    for (int c = 0; c < NCH; c++) {
        if (c + 1 < NCH) {
            uint32_t ab = sbase + ((c + 1) & 1) * STAGE_BYTES;
            int kof = (c + 1) * BK;
            #pragma unroll
            for (int s = 0; s < 4; s++) {
                int r = r8 + s * 32;
                uint32_t off = (uint32_t)(r * SSTR + q8 * 4) * 4;
                cp16(ab + off, &E[(size_t)(i0 + r) * FDIM + kof + q8 * 4]);
                int wr = j0 + r; if (wr >= NCLS) wr = NCLS - 1;
                cp16(ab + BM * SSTR * 4 + off, &W[(size_t)wr * FDIM + kof + q8 * 4]);
            }
            cp_commit();
            cp_wait<1>();
        } else {
            cp_wait<0>();
        }
        __syncthreads();
        const float (*cA)[SSTR] = (const float (*)[SSTR])(dynsm + (c & 1) * STAGE_FLOATS);
        const float (*cB)[SSTR] = (const float (*)[SSTR])(dynsm + (c & 1) * STAGE_FLOATS + BM * SSTR);
        #pragma unroll
        for (int k8 = 0; k8 < 4; k8++) {
            int kc = k8 * 8;
            uint32_t af[2][4];
            #pragma unroll
            for (int mt = 0; mt < 2; mt++) {
                int r = wm * 32 + mt * 16;
                af[mt][0] = __float_as_uint(cA[r + g    ][kc + tg    ]);
                af[mt][1] = __float_as_uint(cA[r + g + 8][kc + tg    ]);
                af[mt][2] = __float_as_uint(cA[r + g    ][kc + tg + 4]);
                af[mt][3] = __float_as_uint(cA[r + g + 8][kc + tg + 4]);
            }
            #pragma unroll
            for (int nt = 0; nt < 8; nt++) {
                int rn = wn * 64 + nt * 8;
                uint32_t b0 = __float_as_uint(cB[rn + g][kc + tg    ]);
                uint32_t b1 = __float_as_uint(cB[rn + g][kc + tg + 4]);
                mma_tf32(acc[0][nt], af[0], b0, b1);
                mma_tf32(acc[1][nt], af[1], b0, b1);
            }
        }
        __syncthreads();
    }

    // epilogue: masked bias-add, per-(row, warp-half) partial (max, sumexp)
    #pragma unroll
    for (int mt = 0; mt < 2; mt++) {
        #pragma unroll
        for (int half = 0; half < 2; half++) {
            int lr = wm * 32 + mt * 16 + g + half * 8;
            int irow = i0 + lr;
            int lab  = sLab[lr];
            float v[16];
            float m = -INFINITY;
            #pragma unroll
            for (int nt = 0; nt < 8; nt++) {
                #pragma unroll
                for (int e = 0; e < 2; e++) {
                    int lc  = wn * 64 + nt * 8 + 2 * tg + e;
                    int col = j0 + lc;
                    float x = (col < NCLS) ? (acc[mt][nt][half * 2 + e] + sBias[lc]) : -INFINITY;
                    if (col == lab) g_ref[irow] = x;
                    v[nt * 2 + e] = x;
                    m = fmaxf(m, x);
                }
            }
            m = fmaxf(m, __shfl_xor_sync(0xffffffff, m, 1));
            m = fmaxf(m, __shfl_xor_sync(0xffffffff, m, 2));
            float s = 0.f;
            #pragma unroll
            for (int q = 0; q < 16; q++) s += __expf(v[q] - m);
            s += __shfl_xor_sync(0xffffffff, s, 1);
            s += __shfl_xor_sync(0xffffffff, s, 2);
            if (tg == 0) { g_pm[irow][jt * 2 + wn] = m; g_ps[irow][jt * 2 + wn] = s; }
        }
    }
}

// ---------------- final: CE merge + total loss (deterministic) ----------------
__global__ void final_kernel(float* __restrict__ out) {
    int t = threadIdx.x;   // 256
    float l = 0.f;
    for (int i = t; i < BATCH; i += 256) {
        float M = -INFINITY;
        #pragma unroll
        for (int k = 0; k < NJT2; k++) M = fmaxf(M, g_pm[i][k]);
        float S = 0.f;
        #pragma unroll
        for (int k = 0; k < NJT2; k++) S += g_ps[i][k] * expf(g_pm[i][k] - M);
        float ce = M + logf(S) - g_ref[i];
        float ap = __uint_as_float(g_ap[i]);
        float an = __uint_as_float(g_an[i]);
        l += fmaxf(ap - an + MARGIN, 0.f) + LAMBDA * g_cent[i] + ce;
    }
    __shared__ float red[256];
    red[t] = l;
    __syncthreads();
    for (int off = 128; off > 0; off >>= 1) {
        if (t < off) red[t] += red[t + off];
        __syncthreads();
    }
    if (t == 0) out[0] = red[0] / (float)BATCH;
}

// ---------------- launch ----------------
extern "C" void kernel_launch(void* const* d_in, const int* in_sizes, int n_in,
                              void* d_out, int out_size) {
    const float* E    = (const float*)d_in[0];
    const void*  labs = d_in[1];
    const float* Ctr  = (const float*)d_in[2];
    const float* W    = (const float*)d_in[3];
    const float* bvec = (const float*)d_in[4];
    float* out = (float*)d_out;

    // idempotent; persists from the pre-capture correctness call (return ignored in-capture)
    cudaFuncSetAttribute(triplet_mma_kernel, cudaFuncAttributeMaxDynamicSharedMemorySize, DYN_BYTES);
    cudaFuncSetAttribute(ce_mma_kernel,      cudaFuncAttributeMaxDynamicSharedMemorySize, DYN_BYTES);

    detect_kernel<<<1, 256>>>((const long long*)labs);
    prep_center_kernel<<<BATCH, 128>>>(E, labs, Ctr);
    triplet_mma_kernel<<<NTRI, 256, DYN_BYTES>>>(E);
    ce_mma_kernel<<<dim3(BATCH / BM, 1024 / BN), 256, DYN_BYTES>>>(E, W, bvec);
    final_kernel<<<1, 256>>>(out);
}

// round 12
// speedup vs baseline: 9.8866x; 1.2410x over previous
#include <cuda_runtime.h>
#include <cuda_bf16.h>
#include <math.h>
#include <stdint.h>

#define BATCH 4096
#define FDIM  512
#define NCLS  1000
#define MARGIN 0.3f
#define LAMBDA 0.01f
#define EPSV   1e-12f
#define NJT2  16         // CE partials per row: 8 j-tiles x 2 warp-halves

// ---- CE (tf32) tiling: R8-measured-best config ----
#define BM 128
#define BN 128
#define BK 32
#define SSTR 36                          // fp32 smem row stride (floats)
#define STAGE_FLOATS ((BM + BN) * SSTR)  // 9216
#define STAGE_BYTES  (STAGE_FLOATS * 4)  // 36864
#define DYN_BYTES    (2 * STAGE_BYTES)   // 73728

// ---- triplet (bf16) tiling ----
#define BKT 64
#define NCHT (FDIM / BKT)                // 8
#define SSTRW 36                         // words per bf16 row (64 bf16 = 32 words + 4 pad)
#define TSTAGE_BYTES (256 * SSTRW * 4)   // 36864
#define TDYN_BYTES   (2 * TSTAGE_BYTES)  // 73728

#define NTILE (BATCH / BM)               // 32
#define NTRI  (NTILE * (NTILE + 1) / 2)  // 528

// ---------------- device scratch ----------------
__device__ float        g_sq[BATCH];
__device__ int          g_lab[BATCH];
__device__ unsigned int g_ap[BATCH];
__device__ unsigned int g_an[BATCH];
__device__ float        g_cent[BATCH];
__device__ float        g_pm[BATCH][NJT2];
__device__ float        g_ps[BATCH][NJT2];
__device__ float        g_ref[BATCH];
__device__ int          g_labmode;
__device__ __align__(16) uint4 g_ebf4[BATCH * FDIM / 8];   // E in bf16 (4 MB)

// ---------------- helpers ----------------
__device__ __forceinline__ uint32_t smem_u32(const void* p) {
    uint32_t a;
    asm("{ .reg .u64 t; cvta.to.shared.u64 t, %1; cvt.u32.u64 %0, t; }" : "=r"(a) : "l"(p));
    return a;
}
__device__ __forceinline__ void cp16(uint32_t dst, const void* src) {
    asm volatile("cp.async.cg.shared.global [%0], [%1], 16;" :: "r"(dst), "l"(src));
}
__device__ __forceinline__ void cp_commit() {
    asm volatile("cp.async.commit_group;" ::: "memory");
}
template<int N> __device__ __forceinline__ void cp_wait() {
    asm volatile("cp.async.wait_group %0;" :: "n"(N) : "memory");
}
__device__ __forceinline__ void mma_tf32(float* c, const uint32_t* a, uint32_t b0, uint32_t b1) {
    asm volatile(
        "mma.sync.aligned.m16n8k8.row.col.f32.tf32.tf32.f32 "
        "{%0,%1,%2,%3}, {%4,%5,%6,%7}, {%8,%9}, {%0,%1,%2,%3};"
        : "+f"(c[0]), "+f"(c[1]), "+f"(c[2]), "+f"(c[3])
        : "r"(a[0]), "r"(a[1]), "r"(a[2]), "r"(a[3]), "r"(b0), "r"(b1));
}
__device__ __forceinline__ void mma_bf16(float* c, const uint32_t* a, uint32_t b0, uint32_t b1) {
    asm volatile(
        "mma.sync.aligned.m16n8k16.row.col.f32.bf16.bf16.f32 "
        "{%0,%1,%2,%3}, {%4,%5,%6,%7}, {%8,%9}, {%0,%1,%2,%3};"
        : "+f"(c[0]), "+f"(c[1]), "+f"(c[2]), "+f"(c[3])
        : "r"(a[0]), "r"(a[1]), "r"(a[2]), "r"(a[3]), "r"(b0), "r"(b1));
}

// ---------------- label dtype detection ----------------
__global__ void detect_kernel(const long long* __restrict__ lab64) {
    __shared__ int bad;
    if (threadIdx.x == 0) bad = 0;
    __syncthreads();
    int mybad = 0;
    for (int i = threadIdx.x; i < 2048; i += blockDim.x) {
        long long v = lab64[i];
        if (v < 0 || v >= NCLS) mybad = 1;
    }
    if (mybad) atomicOr(&bad, 1);
    __syncthreads();
    if (threadIdx.x == 0) g_labmode = bad ? 1 : 0;
}

// ---------------- fused prep + center + bf16 convert: one pass over E ----------------
__global__ void prep_center_kernel(const float* __restrict__ E, const void* __restrict__ labels,
                                   const float* __restrict__ Ctr) {
    int i = blockIdx.x;
    int t = threadIdx.x;    // 128
    __shared__ int slab;
    if (t == 0) {
        int lab;
        if (g_labmode == 0) lab = (int)((const long long*)labels)[i];
        else                lab = ((const int*)labels)[i];
        g_lab[i] = lab;
        slab = lab;
        g_ap[i] = 0u;
        g_an[i] = 0x7f800000u;
    }
    __syncthreads();
    int lab = slab;
    const float4* e4 = (const float4*)(E   + (size_t)i   * FDIM);
    const float4* c4 = (const float4*)(Ctr + (size_t)lab * FDIM);
    float4 v = e4[t];
    float4 cc = c4[t];
    float sq = v.x * v.x + v.y * v.y + v.z * v.z + v.w * v.w;
    float dx = v.x - cc.x, dy = v.y - cc.y, dz = v.z - cc.z, dw = v.w - cc.w;
    float cd = dx * dx + dy * dy + dz * dz + dw * dw;
    // bf16 conversion: low half = smaller k
    __nv_bfloat162 h0 = __floats2bfloat162_rn(v.x, v.y);
    __nv_bfloat162 h1 = __floats2bfloat162_rn(v.z, v.w);
    uint2 packed;
    packed.x = *(uint32_t*)&h0;
    packed.y = *(uint32_t*)&h1;
    ((uint2*)g_ebf4)[(size_t)i * (FDIM / 4) + t] = packed;

    for (int off = 16; off > 0; off >>= 1) {
        sq += __shfl_xor_sync(0xffffffff, sq, off);
        cd += __shfl_xor_sync(0xffffffff, cd, off);
    }
    __shared__ float wsq[4], wcd[4];
    if ((t & 31) == 0) { wsq[t >> 5] = sq; wcd[t >> 5] = cd; }
    __syncthreads();
    if (t == 0) {
        g_sq[i]   = wsq[0] + wsq[1] + wsq[2] + wsq[3];
        g_cent[i] = wcd[0] + wcd[1] + wcd[2] + wcd[3];
    }
}

// ---------------- triplet: symmetric bf16 Gram (m16n8k16), dual epilogue ----------------
__global__ __launch_bounds__(256, 2) void triplet_mma_kernel() {
    extern __shared__ float dynsm[];
    __shared__ float sQi[BM]; __shared__ int sLi[BM];
    __shared__ float sQj[BN]; __shared__ int sLj[BN];

    // triangular decode: block -> (bi, bj) with bj >= bi
    int rem = blockIdx.x, bi = 0;
    #pragma unroll 1
    for (;;) { int len = NTILE - bi; if (rem < len) break; rem -= len; bi++; }
    int bj = bi + rem;
    bool diag = (bi == bj);

    int t = threadIdx.x;
    int lane = t & 31, wid = t >> 5;
    int wm = wid >> 1, wn = wid & 1;
    int g = lane >> 2, tg = lane & 3;
    int i0 = bi * BM, j0 = bj * BN;

    uint32_t sbase = smem_u32(dynsm);
    const char* ebf = (const char*)g_ebf4;

    if (t < BM)            { sQi[t] = g_sq[i0 + t]; sLi[t] = g_lab[i0 + t]; }
    else if (t < BM + BN)  { int u = t - BM; sQj[u] = g_sq[j0 + u]; sLj[u] = g_lab[j0 + u]; }

    // prologue: chunk 0 -> stage 0.  256 rows x 64 bf16; 8 segs of 16B per row.
    {
        #pragma unroll
        for (int s = 0; s < 8; s++) {
            int f = t + s * 256;
            int row = f >> 3, seg = f & 7;
            int grow = (row < 128) ? (i0 + row) : (j0 + row - 128);
            uint32_t dst = sbase + (uint32_t)(row * (SSTRW * 4) + seg * 16);
            cp16(dst, ebf + ((size_t)grow * FDIM + seg * 8) * 2);
        }
        cp_commit();
    }

    float acc[2][8][4];
    #pragma unroll
    for (int mt = 0; mt < 2; mt++)
        #pragma unroll
        for (int nt = 0; nt < 8; nt++)
            #pragma unroll
            for (int e = 0; e < 4; e++) acc[mt][nt][e] = 0.f;

    #pragma unroll 1
    for (int c = 0; c < NCHT; c++) {
        if (c + 1 < NCHT) {
            uint32_t ab = sbase + ((c + 1) & 1) * TSTAGE_BYTES;
            int kof = (c + 1) * BKT;
            #pragma unroll
            for (int s = 0; s < 8; s++) {
                int f = t + s * 256;
                int row = f >> 3, seg = f & 7;
                int grow = (row < 128) ? (i0 + row) : (j0 + row - 128);
                uint32_t dst = ab + (uint32_t)(row * (SSTRW * 4) + seg * 16);
                cp16(dst, ebf + ((size_t)grow * FDIM + kof + seg * 8) * 2);
            }
            cp_commit();
            cp_wait<1>();
        } else {
            cp_wait<0>();
        }
        __syncthreads();
        const uint32_t* st = (const uint32_t*)((const char*)dynsm + (c & 1) * TSTAGE_BYTES);
        #pragma unroll
        for (int k16 = 0; k16 < 4; k16++) {
            int w0 = k16 * 8;
            uint32_t af[2][4];
            #pragma unroll
            for (int mt = 0; mt < 2; mt++) {
                const uint32_t* ba = st + (wm * 32 + mt * 16 + g) * SSTRW + w0;
                af[mt][0] = ba[tg];
                af[mt][1] = ba[8 * SSTRW + tg];
                af[mt][2] = ba[tg + 4];
                af[mt][3] = ba[8 * SSTRW + tg + 4];
            }
            #pragma unroll
            for (int nt = 0; nt < 8; nt++) {
                const uint32_t* bb = st + (128 + wn * 64 + nt * 8 + g) * SSTRW + w0;
                uint32_t b0 = bb[tg];
                uint32_t b1 = bb[tg + 4];
                mma_bf16(acc[0][nt], af[0], b0, b1);
                mma_bf16(acc[1][nt], af[1], b0, b1);
            }
        }
        __syncthreads();   // all warps done with stage (c&1) before chunk c+2 overwrites
    }

    // ---- dual-sided epilogue ----
    float rap[4], ran[4];
    float cap[16], can[16];
    #pragma unroll
    for (int s4 = 0; s4 < 4; s4++) { rap[s4] = 0.f; ran[s4] = INFINITY; }
    #pragma unroll
    for (int cs = 0; cs < 16; cs++) { cap[cs] = 0.f; can[cs] = INFINITY; }

    #pragma unroll
    for (int mt = 0; mt < 2; mt++) {
        #pragma unroll
        for (int half = 0; half < 2; half++) {
            int lr = wm * 32 + mt * 16 + g + half * 8;
            float qi = sQi[lr]; int li = sLi[lr];
            int slot = mt * 2 + half;
            #pragma unroll
            for (int nt = 0; nt < 8; nt++) {
                #pragma unroll
                for (int e = 0; e < 2; e++) {
                    int lc = wn * 64 + nt * 8 + 2 * tg + e;
                    float d2 = qi + sQj[lc] - 2.f * acc[mt][nt][half * 2 + e];
                    float dist = sqrtf(fmaxf(d2, EPSV));
                    bool same = (sLj[lc] == li);
                    if (same) rap[slot] = fmaxf(rap[slot], dist);
                    else      ran[slot] = fminf(ran[slot], dist);
                    if (!diag) {
                        int cs = nt * 2 + e;
                        if (same) cap[cs] = fmaxf(cap[cs], dist);
                        else      can[cs] = fminf(can[cs], dist);
                    }
                }
            }
        }
    }

    // rows: reduce over tg (lane bits 0..1)
    #pragma unroll
    for (int s4 = 0; s4 < 4; s4++) {
        rap[s4] = fmaxf(rap[s4], __shfl_xor_sync(0xffffffff, rap[s4], 1));
        rap[s4] = fmaxf(rap[s4], __shfl_xor_sync(0xffffffff, rap[s4], 2));
        ran[s4] = fminf(ran[s4], __shfl_xor_sync(0xffffffff, ran[s4], 1));
        ran[s4] = fminf(ran[s4], __shfl_xor_sync(0xffffffff, ran[s4], 2));
    }
    if (tg == 0) {
        #pragma unroll
        for (int s4 = 0; s4 < 4; s4++) {
            int lr = wm * 32 + (s4 >> 1) * 16 + g + (s4 & 1) * 8;
            atomicMax(&g_ap[i0 + lr], __float_as_uint(rap[s4]));
            atomicMin(&g_an[i0 + lr], __float_as_uint(ran[s4]));
        }
    }
    // columns: reduce over g (lane bits 2..4)
    if (!diag) {
        #pragma unroll
        for (int cs = 0; cs < 16; cs++) {
            cap[cs] = fmaxf(cap[cs], __shfl_xor_sync(0xffffffff, cap[cs], 4));
            cap[cs] = fmaxf(cap[cs], __shfl_xor_sync(0xffffffff, cap[cs], 8));
            cap[cs] = fmaxf(cap[cs], __shfl_xor_sync(0xffffffff, cap[cs], 16));
            can[cs] = fminf(can[cs], __shfl_xor_sync(0xffffffff, can[cs], 4));
            can[cs] = fminf(can[cs], __shfl_xor_sync(0xffffffff, can[cs], 8));
            can[cs] = fminf(can[cs], __shfl_xor_sync(0xffffffff, can[cs], 16));
        }
        if (lane < 4) {   // g == 0; tg == lane
            #pragma unroll
            for (int cs = 0; cs < 16; cs++) {
                int col = j0 + wn * 64 + (cs >> 1) * 8 + 2 * lane + (cs & 1);
                atomicMax(&g_ap[col], __float_as_uint(cap[cs]));
                atomicMin(&g_an[col], __float_as_uint(can[cs]));
            }
        }
    }
}

// ---------------- CE: tf32 logits, R8 pipeline (BK=32, 2-stage) — unchanged ----------------
__global__ __launch_bounds__(256, 2) void ce_mma_kernel(const float* __restrict__ E,
                                                        const float* __restrict__ W,
                                                        const float* __restrict__ bvec) {
    extern __shared__ float dynsm[];
    __shared__ float sBias[BN];
    __shared__ int   sLab[BM];

    int t = threadIdx.x;
    int lane = t & 31, wid = t >> 5;
    int wm = wid >> 1, wn = wid & 1;
    int g = lane >> 2, tg = lane & 3;
    int i0 = blockIdx.x * BM, j0 = blockIdx.y * BN;
    int jt = blockIdx.y;

    uint32_t sbase = smem_u32(dynsm);
    int r8 = t >> 3, q8 = t & 7;

    if (t < BN)           { int cls = j0 + t; sBias[t] = bvec[cls < NCLS ? cls : NCLS - 1]; }
    else if (t < BN + BM) { sLab[t - BN] = g_lab[i0 + (t - BN)]; }

    {
        uint32_t ab = sbase;
        #pragma unroll
        for (int s = 0; s < 4; s++) {
            int r = r8 + s * 32;
            uint32_t off = (uint32_t)(r * SSTR + q8 * 4) * 4;
            cp16(ab + off, &E[(size_t)(i0 + r) * FDIM + q8 * 4]);
            int wr = j0 + r; if (wr >= NCLS) wr = NCLS - 1;
            cp16(ab + BM * SSTR * 4 + off, &W[(size_t)wr * FDIM + q8 * 4]);
        }
        cp_commit();
    }

    float acc[2][8][4];
    #pragma unroll
    for (int mt = 0; mt < 2; mt++)
        #pragma unroll
        for (int nt = 0; nt < 8; nt++)
            #pragma unroll
            for (int e = 0; e < 4; e++) acc[mt][nt][e] = 0.f;

    const int NCH = FDIM / BK;
    #pragma unroll 1
    for (int c = 0; c < NCH; c++) {
        if (c + 1 < NCH) {
            uint32_t ab = sbase + ((c + 1) & 1) * STAGE_BYTES;
            int kof = (c + 1) * BK;
            #pragma unroll
            for (int s = 0; s < 4; s++) {
                int r = r8 + s * 32;
                uint32_t off = (uint32_t)(r * SSTR + q8 * 4) * 4;
                cp16(ab + off, &E[(size_t)(i0 + r) * FDIM + kof + q8 * 4]);
                int wr = j0 + r; if (wr >= NCLS) wr = NCLS - 1;
                cp16(ab + BM * SSTR * 4 + off, &W[(size_t)wr * FDIM + kof + q8 * 4]);
            }
            cp_commit();
            cp_wait<1>();
        } else {
            cp_wait<0>();
        }
        __syncthreads();
        const float (*cA)[SSTR] = (const float (*)[SSTR])(dynsm + (c & 1) * STAGE_FLOATS);
        const float (*cB)[SSTR] = (const float (*)[SSTR])(dynsm + (c & 1) * STAGE_FLOATS + BM * SSTR);
        #pragma unroll
        for (int k8 = 0; k8 < 4; k8++) {
            int kc = k8 * 8;
            uint32_t af[2][4];
            #pragma unroll
            for (int mt = 0; mt < 2; mt++) {
                int r = wm * 32 + mt * 16;
                af[mt][0] = __float_as_uint(cA[r + g    ][kc + tg    ]);
                af[mt][1] = __float_as_uint(cA[r + g + 8][kc + tg    ]);
                af[mt][2] = __float_as_uint(cA[r + g    ][kc + tg + 4]);
                af[mt][3] = __float_as_uint(cA[r + g + 8][kc + tg + 4]);
            }
            #pragma unroll
            for (int nt = 0; nt < 8; nt++) {
                int rn = wn * 64 + nt * 8;
                uint32_t b0 = __float_as_uint(cB[rn + g][kc + tg    ]);
                uint32_t b1 = __float_as_uint(cB[rn + g][kc + tg + 4]);
                mma_tf32(acc[0][nt], af[0], b0, b1);
                mma_tf32(acc[1][nt], af[1], b0, b1);
            }
        }
        __syncthreads();
    }

    // epilogue: masked bias-add, per-(row, warp-half) partial (max, sumexp)
    #pragma unroll
    for (int mt = 0; mt < 2; mt++) {
        #pragma unroll
        for (int half = 0; half < 2; half++) {
            int lr = wm * 32 + mt * 16 + g + half * 8;
            int irow = i0 + lr;
            int lab  = sLab[lr];
            float v[16];
            float m = -INFINITY;
            #pragma unroll
            for (int nt = 0; nt < 8; nt++) {
                #pragma unroll
                for (int e = 0; e < 2; e++) {
                    int lc  = wn * 64 + nt * 8 + 2 * tg + e;
                    int col = j0 + lc;
                    float x = (col < NCLS) ? (acc[mt][nt][half * 2 + e] + sBias[lc]) : -INFINITY;
                    if (col == lab) g_ref[irow] = x;
                    v[nt * 2 + e] = x;
                    m = fmaxf(m, x);
                }
            }
            m = fmaxf(m, __shfl_xor_sync(0xffffffff, m, 1));
            m = fmaxf(m, __shfl_xor_sync(0xffffffff, m, 2));
            float s = 0.f;
            #pragma unroll
            for (int q = 0; q < 16; q++) s += __expf(v[q] - m);
            s += __shfl_xor_sync(0xffffffff, s, 1);
            s += __shfl_xor_sync(0xffffffff, s, 2);
            if (tg == 0) { g_pm[irow][jt * 2 + wn] = m; g_ps[irow][jt * 2 + wn] = s; }
        }
    }
}

// ---------------- final: CE merge + total loss (deterministic) ----------------
__global__ void final_kernel(float* __restrict__ out) {
    int t = threadIdx.x;   // 256
    float l = 0.f;
    for (int i = t; i < BATCH; i += 256) {
        float M = -INFINITY;
        #pragma unroll
        for (int k = 0; k < NJT2; k++) M = fmaxf(M, g_pm[i][k]);
        float S = 0.f;
        #pragma unroll
        for (int k = 0; k < NJT2; k++) S += g_ps[i][k] * expf(g_pm[i][k] - M);
        float ce = M + logf(S) - g_ref[i];
        float ap = __uint_as_float(g_ap[i]);
        float an = __uint_as_float(g_an[i]);
        l += fmaxf(ap - an + MARGIN, 0.f) + LAMBDA * g_cent[i] + ce;
    }
    __shared__ float red[256];
    red[t] = l;
    __syncthreads();
    for (int off = 128; off > 0; off >>= 1) {
        if (t < off) red[t] += red[t + off];
        __syncthreads();
    }
    if (t == 0) out[0] = red[0] / (float)BATCH;
}

// ---------------- launch ----------------
extern "C" void kernel_launch(void* const* d_in, const int* in_sizes, int n_in,
                              void* d_out, int out_size) {
    const float* E    = (const float*)d_in[0];
    const void*  labs = d_in[1];
    const float* Ctr  = (const float*)d_in[2];
    const float* W    = (const float*)d_in[3];
    const float* bvec = (const float*)d_in[4];
    float* out = (float*)d_out;

    // idempotent; persists from the pre-capture correctness call (return ignored in-capture)
    cudaFuncSetAttribute(triplet_mma_kernel, cudaFuncAttributeMaxDynamicSharedMemorySize, TDYN_BYTES);
    cudaFuncSetAttribute(ce_mma_kernel,      cudaFuncAttributeMaxDynamicSharedMemorySize, DYN_BYTES);

    detect_kernel<<<1, 256>>>((const long long*)labs);
    prep_center_kernel<<<BATCH, 128>>>(E, labs, Ctr);
    triplet_mma_kernel<<<NTRI, 256, TDYN_BYTES>>>();
    ce_mma_kernel<<<dim3(BATCH / BM, 1024 / BN), 256, DYN_BYTES>>>(E, W, bvec);
    final_kernel<<<1, 256>>>(out);
}

// round 13
// speedup vs baseline: 11.1548x; 1.1283x over previous
#include <cuda_runtime.h>
#include <cuda_bf16.h>
#include <math.h>
#include <stdint.h>

#define BATCH 4096
#define FDIM  512
#define NCLS  1000
#define MARGIN 0.3f
#define LAMBDA 0.01f
#define EPSV   1e-12f
#define NJT2  16         // CE partials per row: 8 j-tiles x 2 warp-halves

#define BM 128
#define BN 128

// ---- bf16 tiling (shared by triplet + CE) ----
#define BKT 64
#define NCHT (FDIM / BKT)                // 8
#define SSTRW 36                         // words per bf16 row (64 bf16 = 32 words + 4 pad)
#define TSTAGE_BYTES (256 * SSTRW * 4)   // 36864
#define TDYN_BYTES   (2 * TSTAGE_BYTES)  // 73728

#define NTILE (BATCH / BM)               // 32
#define NTRI  (NTILE * (NTILE + 1) / 2)  // 528

// ---------------- device scratch ----------------
__device__ float        g_sq[BATCH];
__device__ int          g_lab[BATCH];
__device__ unsigned int g_ap[BATCH];
__device__ unsigned int g_an[BATCH];
__device__ float        g_cent[BATCH];
__device__ float        g_pm[BATCH][NJT2];
__device__ float        g_ps[BATCH][NJT2];
__device__ float        g_ref[BATCH];
__device__ int          g_labmode;
__device__ __align__(16) uint4 g_ebf4[BATCH * FDIM / 8];   // E in bf16 (4 MB)
__device__ __align__(16) uint4 g_wbf4[NCLS * FDIM / 8];    // W in bf16 (1 MB)

// ---------------- helpers ----------------
__device__ __forceinline__ uint32_t smem_u32(const void* p) {
    uint32_t a;
    asm("{ .reg .u64 t; cvta.to.shared.u64 t, %1; cvt.u32.u64 %0, t; }" : "=r"(a) : "l"(p));
    return a;
}
__device__ __forceinline__ void cp16(uint32_t dst, const void* src) {
    asm volatile("cp.async.cg.shared.global [%0], [%1], 16;" :: "r"(dst), "l"(src));
}
__device__ __forceinline__ void cp_commit() {
    asm volatile("cp.async.commit_group;" ::: "memory");
}
template<int N> __device__ __forceinline__ void cp_wait() {
    asm volatile("cp.async.wait_group %0;" :: "n"(N) : "memory");
}
__device__ __forceinline__ void mma_bf16(float* c, const uint32_t* a, uint32_t b0, uint32_t b1) {
    asm volatile(
        "mma.sync.aligned.m16n8k16.row.col.f32.bf16.bf16.f32 "
        "{%0,%1,%2,%3}, {%4,%5,%6,%7}, {%8,%9}, {%0,%1,%2,%3};"
        : "+f"(c[0]), "+f"(c[1]), "+f"(c[2]), "+f"(c[3])
        : "r"(a[0]), "r"(a[1]), "r"(a[2]), "r"(a[3]), "r"(b0), "r"(b1));
}

// ---------------- label dtype detection ----------------
__global__ void detect_kernel(const long long* __restrict__ lab64) {
    __shared__ int bad;
    if (threadIdx.x == 0) bad = 0;
    __syncthreads();
    int mybad = 0;
    for (int i = threadIdx.x; i < 2048; i += blockDim.x) {
        long long v = lab64[i];
        if (v < 0 || v >= NCLS) mybad = 1;
    }
    if (mybad) atomicOr(&bad, 1);
    __syncthreads();
    if (threadIdx.x == 0) g_labmode = bad ? 1 : 0;
}

// ---------------- W -> bf16 convert ----------------
__global__ void wconv_kernel(const float* __restrict__ W) {
    int idx = blockIdx.x * blockDim.x + threadIdx.x;   // 128000 float4s
    if (idx >= NCLS * FDIM / 4) return;
    float4 v = ((const float4*)W)[idx];
    __nv_bfloat162 h0 = __floats2bfloat162_rn(v.x, v.y);
    __nv_bfloat162 h1 = __floats2bfloat162_rn(v.z, v.w);
    uint2 packed;
    packed.x = *(uint32_t*)&h0;
    packed.y = *(uint32_t*)&h1;
    ((uint2*)g_wbf4)[idx] = packed;
}

// ---------------- fused prep + center + bf16 convert: one pass over E ----------------
__global__ void prep_center_kernel(const float* __restrict__ E, const void* __restrict__ labels,
                                   const float* __restrict__ Ctr) {
    int i = blockIdx.x;
    int t = threadIdx.x;    // 128
    __shared__ int slab;
    if (t == 0) {
        int lab;
        if (g_labmode == 0) lab = (int)((const long long*)labels)[i];
        else                lab = ((const int*)labels)[i];
        g_lab[i] = lab;
        slab = lab;
        g_ap[i] = 0u;
        g_an[i] = 0x7f800000u;
    }
    __syncthreads();
    int lab = slab;
    const float4* e4 = (const float4*)(E   + (size_t)i   * FDIM);
    const float4* c4 = (const float4*)(Ctr + (size_t)lab * FDIM);
    float4 v = e4[t];
    float4 cc = c4[t];
    float sq = v.x * v.x + v.y * v.y + v.z * v.z + v.w * v.w;
    float dx = v.x - cc.x, dy = v.y - cc.y, dz = v.z - cc.z, dw = v.w - cc.w;
    float cd = dx * dx + dy * dy + dz * dz + dw * dw;
    __nv_bfloat162 h0 = __floats2bfloat162_rn(v.x, v.y);
    __nv_bfloat162 h1 = __floats2bfloat162_rn(v.z, v.w);
    uint2 packed;
    packed.x = *(uint32_t*)&h0;
    packed.y = *(uint32_t*)&h1;
    ((uint2*)g_ebf4)[(size_t)i * (FDIM / 4) + t] = packed;

    for (int off = 16; off > 0; off >>= 1) {
        sq += __shfl_xor_sync(0xffffffff, sq, off);
        cd += __shfl_xor_sync(0xffffffff, cd, off);
    }
    __shared__ float wsq[4], wcd[4];
    if ((t & 31) == 0) { wsq[t >> 5] = sq; wcd[t >> 5] = cd; }
    __syncthreads();
    if (t == 0) {
        g_sq[i]   = wsq[0] + wsq[1] + wsq[2] + wsq[3];
        g_cent[i] = wcd[0] + wcd[1] + wcd[2] + wcd[3];
    }
}

// ---------------- triplet: symmetric bf16 Gram (m16n8k16), dual epilogue ----------------
__global__ __launch_bounds__(256, 2) void triplet_mma_kernel() {
    extern __shared__ float dynsm[];
    __shared__ float sQi[BM]; __shared__ int sLi[BM];
    __shared__ float sQj[BN]; __shared__ int sLj[BN];

    int rem = blockIdx.x, bi = 0;
    #pragma unroll 1
    for (;;) { int len = NTILE - bi; if (rem < len) break; rem -= len; bi++; }
    int bj = bi + rem;
    bool diag = (bi == bj);

    int t = threadIdx.x;
    int lane = t & 31, wid = t >> 5;
    int wm = wid >> 1, wn = wid & 1;
    int g = lane >> 2, tg = lane & 3;
    int i0 = bi * BM, j0 = bj * BN;

    uint32_t sbase = smem_u32(dynsm);
    const char* ebf = (const char*)g_ebf4;

    if (t < BM)            { sQi[t] = g_sq[i0 + t]; sLi[t] = g_lab[i0 + t]; }
    else if (t < BM + BN)  { int u = t - BM; sQj[u] = g_sq[j0 + u]; sLj[u] = g_lab[j0 + u]; }

    {
        #pragma unroll
        for (int s = 0; s < 8; s++) {
            int f = t + s * 256;
            int row = f >> 3, seg = f & 7;
            int grow = (row < 128) ? (i0 + row) : (j0 + row - 128);
            uint32_t dst = sbase + (uint32_t)(row * (SSTRW * 4) + seg * 16);
            cp16(dst, ebf + ((size_t)grow * FDIM + seg * 8) * 2);
        }
        cp_commit();
    }

    float acc[2][8][4];
    #pragma unroll
    for (int mt = 0; mt < 2; mt++)
        #pragma unroll
        for (int nt = 0; nt < 8; nt++)
            #pragma unroll
            for (int e = 0; e < 4; e++) acc[mt][nt][e] = 0.f;

    #pragma unroll 1
    for (int c = 0; c < NCHT; c++) {
        if (c + 1 < NCHT) {
            uint32_t ab = sbase + ((c + 1) & 1) * TSTAGE_BYTES;
            int kof = (c + 1) * BKT;
            #pragma unroll
            for (int s = 0; s < 8; s++) {
                int f = t + s * 256;
                int row = f >> 3, seg = f & 7;
                int grow = (row < 128) ? (i0 + row) : (j0 + row - 128);
                uint32_t dst = ab + (uint32_t)(row * (SSTRW * 4) + seg * 16);
                cp16(dst, ebf + ((size_t)grow * FDIM + kof + seg * 8) * 2);
            }
            cp_commit();
            cp_wait<1>();
        } else {
            cp_wait<0>();
        }
        __syncthreads();
        const uint32_t* st = (const uint32_t*)((const char*)dynsm + (c & 1) * TSTAGE_BYTES);
        #pragma unroll
        for (int k16 = 0; k16 < 4; k16++) {
            int w0 = k16 * 8;
            uint32_t af[2][4];
            #pragma unroll
            for (int mt = 0; mt < 2; mt++) {
                const uint32_t* ba = st + (wm * 32 + mt * 16 + g) * SSTRW + w0;
                af[mt][0] = ba[tg];
                af[mt][1] = ba[8 * SSTRW + tg];
                af[mt][2] = ba[tg + 4];
                af[mt][3] = ba[8 * SSTRW + tg + 4];
            }
            #pragma unroll
            for (int nt = 0; nt < 8; nt++) {
                const uint32_t* bb = st + (128 + wn * 64 + nt * 8 + g) * SSTRW + w0;
                uint32_t b0 = bb[tg];
                uint32_t b1 = bb[tg + 4];
                mma_bf16(acc[0][nt], af[0], b0, b1);
                mma_bf16(acc[1][nt], af[1], b0, b1);
            }
        }
        __syncthreads();
    }

    // ---- dual-sided epilogue ----
    float rap[4], ran[4];
    float cap[16], can[16];
    #pragma unroll
    for (int s4 = 0; s4 < 4; s4++) { rap[s4] = 0.f; ran[s4] = INFINITY; }
    #pragma unroll
    for (int cs = 0; cs < 16; cs++) { cap[cs] = 0.f; can[cs] = INFINITY; }

    #pragma unroll
    for (int mt = 0; mt < 2; mt++) {
        #pragma unroll
        for (int half = 0; half < 2; half++) {
            int lr = wm * 32 + mt * 16 + g + half * 8;
            float qi = sQi[lr]; int li = sLi[lr];
            int slot = mt * 2 + half;
            #pragma unroll
            for (int nt = 0; nt < 8; nt++) {
                #pragma unroll
                for (int e = 0; e < 2; e++) {
                    int lc = wn * 64 + nt * 8 + 2 * tg + e;
                    float d2 = qi + sQj[lc] - 2.f * acc[mt][nt][half * 2 + e];
                    float dist = sqrtf(fmaxf(d2, EPSV));
                    bool same = (sLj[lc] == li);
                    if (same) rap[slot] = fmaxf(rap[slot], dist);
                    else      ran[slot] = fminf(ran[slot], dist);
                    if (!diag) {
                        int cs = nt * 2 + e;
                        if (same) cap[cs] = fmaxf(cap[cs], dist);
                        else      can[cs] = fminf(can[cs], dist);
                    }
                }
            }
        }
    }

    #pragma unroll
    for (int s4 = 0; s4 < 4; s4++) {
        rap[s4] = fmaxf(rap[s4], __shfl_xor_sync(0xffffffff, rap[s4], 1));
        rap[s4] = fmaxf(rap[s4], __shfl_xor_sync(0xffffffff, rap[s4], 2));
        ran[s4] = fminf(ran[s4], __shfl_xor_sync(0xffffffff, ran[s4], 1));
        ran[s4] = fminf(ran[s4], __shfl_xor_sync(0xffffffff, ran[s4], 2));
    }
    if (tg == 0) {
        #pragma unroll
        for (int s4 = 0; s4 < 4; s4++) {
            int lr = wm * 32 + (s4 >> 1) * 16 + g + (s4 & 1) * 8;
            atomicMax(&g_ap[i0 + lr], __float_as_uint(rap[s4]));
            atomicMin(&g_an[i0 + lr], __float_as_uint(ran[s4]));
        }
    }
    if (!diag) {
        #pragma unroll
        for (int cs = 0; cs < 16; cs++) {
            cap[cs] = fmaxf(cap[cs], __shfl_xor_sync(0xffffffff, cap[cs], 4));
            cap[cs] = fmaxf(cap[cs], __shfl_xor_sync(0xffffffff, cap[cs], 8));
            cap[cs] = fmaxf(cap[cs], __shfl_xor_sync(0xffffffff, cap[cs], 16));
            can[cs] = fminf(can[cs], __shfl_xor_sync(0xffffffff, can[cs], 4));
            can[cs] = fminf(can[cs], __shfl_xor_sync(0xffffffff, can[cs], 8));
            can[cs] = fminf(can[cs], __shfl_xor_sync(0xffffffff, can[cs], 16));
        }
        if (lane < 4) {
            #pragma unroll
            for (int cs = 0; cs < 16; cs++) {
                int col = j0 + wn * 64 + (cs >> 1) * 8 + 2 * lane + (cs & 1);
                atomicMax(&g_ap[col], __float_as_uint(cap[cs]));
                atomicMin(&g_an[col], __float_as_uint(can[cs]));
            }
        }
    }
}

// ---------------- CE: bf16 logits (m16n8k16), same pipeline as triplet ----------------
__global__ __launch_bounds__(256, 2) void ce_mma_kernel(const float* __restrict__ bvec) {
    extern __shared__ float dynsm[];
    __shared__ float sBias[BN];
    __shared__ int   sLab[BM];

    int t = threadIdx.x;
    int lane = t & 31, wid = t >> 5;
    int wm = wid >> 1, wn = wid & 1;
    int g = lane >> 2, tg = lane & 3;
    int i0 = blockIdx.x * BM, j0 = blockIdx.y * BN;
    int jt = blockIdx.y;

    uint32_t sbase = smem_u32(dynsm);
    const char* ebf = (const char*)g_ebf4;
    const char* wbf = (const char*)g_wbf4;

    if (t < BN)           { int cls = j0 + t; sBias[t] = bvec[cls < NCLS ? cls : NCLS - 1]; }
    else if (t < BN + BM) { sLab[t - BN] = g_lab[i0 + (t - BN)]; }

    {
        #pragma unroll
        for (int s = 0; s < 8; s++) {
            int f = t + s * 256;
            int row = f >> 3, seg = f & 7;
            uint32_t dst = sbase + (uint32_t)(row * (SSTRW * 4) + seg * 16);
            if (row < 128) {
                cp16(dst, ebf + ((size_t)(i0 + row) * FDIM + seg * 8) * 2);
            } else {
                int wr = j0 + row - 128; if (wr >= NCLS) wr = NCLS - 1;
                cp16(dst, wbf + ((size_t)wr * FDIM + seg * 8) * 2);
            }
        }
        cp_commit();
    }

    float acc[2][8][4];
    #pragma unroll
    for (int mt = 0; mt < 2; mt++)
        #pragma unroll
        for (int nt = 0; nt < 8; nt++)
            #pragma unroll
            for (int e = 0; e < 4; e++) acc[mt][nt][e] = 0.f;

    #pragma unroll 1
    for (int c = 0; c < NCHT; c++) {
        if (c + 1 < NCHT) {
            uint32_t ab = sbase + ((c + 1) & 1) * TSTAGE_BYTES;
            int kof = (c + 1) * BKT;
            #pragma unroll
            for (int s = 0; s < 8; s++) {
                int f = t + s * 256;
                int row = f >> 3, seg = f & 7;
                uint32_t dst = ab + (uint32_t)(row * (SSTRW * 4) + seg * 16);
                if (row < 128) {
                    cp16(dst, ebf + ((size_t)(i0 + row) * FDIM + kof + seg * 8) * 2);
                } else {
                    int wr = j0 + row - 128; if (wr >= NCLS) wr = NCLS - 1;
                    cp16(dst, wbf + ((size_t)wr * FDIM + kof + seg * 8) * 2);
                }
            }
            cp_commit();
            cp_wait<1>();
        } else {
            cp_wait<0>();
        }
        __syncthreads();
        const uint32_t* st = (const uint32_t*)((const char*)dynsm + (c & 1) * TSTAGE_BYTES);
        #pragma unroll
        for (int k16 = 0; k16 < 4; k16++) {
            int w0 = k16 * 8;
            uint32_t af[2][4];
            #pragma unroll
            for (int mt = 0; mt < 2; mt++) {
                const uint32_t* ba = st + (wm * 32 + mt * 16 + g) * SSTRW + w0;
                af[mt][0] = ba[tg];
                af[mt][1] = ba[8 * SSTRW + tg];
                af[mt][2] = ba[tg + 4];
                af[mt][3] = ba[8 * SSTRW + tg + 4];
            }
            #pragma unroll
            for (int nt = 0; nt < 8; nt++) {
                const uint32_t* bb = st + (128 + wn * 64 + nt * 8 + g) * SSTRW + w0;
                uint32_t b0 = bb[tg];
                uint32_t b1 = bb[tg + 4];
                mma_bf16(acc[0][nt], af[0], b0, b1);
                mma_bf16(acc[1][nt], af[1], b0, b1);
            }
        }
        __syncthreads();
    }

    // epilogue: masked bias-add, per-(row, warp-half) partial (max, sumexp)
    #pragma unroll
    for (int mt = 0; mt < 2; mt++) {
        #pragma unroll
        for (int half = 0; half < 2; half++) {
            int lr = wm * 32 + mt * 16 + g + half * 8;
            int irow = i0 + lr;
            int lab  = sLab[lr];
            float v[16];
            float m = -INFINITY;
            #pragma unroll
            for (int nt = 0; nt < 8; nt++) {
                #pragma unroll
                for (int e = 0; e < 2; e++) {
                    int lc  = wn * 64 + nt * 8 + 2 * tg + e;
                    int col = j0 + lc;
                    float x = (col < NCLS) ? (acc[mt][nt][half * 2 + e] + sBias[lc]) : -INFINITY;
                    if (col == lab) g_ref[irow] = x;
                    v[nt * 2 + e] = x;
                    m = fmaxf(m, x);
                }
            }
            m = fmaxf(m, __shfl_xor_sync(0xffffffff, m, 1));
            m = fmaxf(m, __shfl_xor_sync(0xffffffff, m, 2));
            float s = 0.f;
            #pragma unroll
            for (int q = 0; q < 16; q++) s += __expf(v[q] - m);
            s += __shfl_xor_sync(0xffffffff, s, 1);
            s += __shfl_xor_sync(0xffffffff, s, 2);
            if (tg == 0) { g_pm[irow][jt * 2 + wn] = m; g_ps[irow][jt * 2 + wn] = s; }
        }
    }
}

// ---------------- final: CE merge + total loss (deterministic) ----------------
__global__ void final_kernel(float* __restrict__ out) {
    int t = threadIdx.x;   // 256
    float l = 0.f;
    for (int i = t; i < BATCH; i += 256) {
        float M = -INFINITY;
        #pragma unroll
        for (int k = 0; k < NJT2; k++) M = fmaxf(M, g_pm[i][k]);
        float S = 0.f;
        #pragma unroll
        for (int k = 0; k < NJT2; k++) S += g_ps[i][k] * expf(g_pm[i][k] - M);
        float ce = M + logf(S) - g_ref[i];
        float ap = __uint_as_float(g_ap[i]);
        float an = __uint_as_float(g_an[i]);
        l += fmaxf(ap - an + MARGIN, 0.f) + LAMBDA * g_cent[i] + ce;
    }
    __shared__ float red[256];
    red[t] = l;
    __syncthreads();
    for (int off = 128; off > 0; off >>= 1) {
        if (t < off) red[t] += red[t + off];
        __syncthreads();
    }
    if (t == 0) out[0] = red[0] / (float)BATCH;
}

// ---------------- launch ----------------
extern "C" void kernel_launch(void* const* d_in, const int* in_sizes, int n_in,
                              void* d_out, int out_size) {
    const float* E    = (const float*)d_in[0];
    const void*  labs = d_in[1];
    const float* Ctr  = (const float*)d_in[2];
    const float* W    = (const float*)d_in[3];
    const float* bvec = (const float*)d_in[4];
    float* out = (float*)d_out;

    cudaFuncSetAttribute(triplet_mma_kernel, cudaFuncAttributeMaxDynamicSharedMemorySize, TDYN_BYTES);
    cudaFuncSetAttribute(ce_mma_kernel,      cudaFuncAttributeMaxDynamicSharedMemorySize, TDYN_BYTES);

    detect_kernel<<<1, 256>>>((const long long*)labs);
    wconv_kernel<<<(NCLS * FDIM / 4 + 255) / 256, 256>>>(W);
    prep_center_kernel<<<BATCH, 128>>>(E, labs, Ctr);
    triplet_mma_kernel<<<NTRI, 256, TDYN_BYTES>>>();
    ce_mma_kernel<<<dim3(BATCH / BM, 1024 / BN), 256, TDYN_BYTES>>>(bvec);
    final_kernel<<<1, 256>>>(out);
}

// round 14
// speedup vs baseline: 11.7319x; 1.0517x over previous
#include <cuda_runtime.h>
#include <cuda_bf16.h>
#include <math.h>
#include <stdint.h>

#define BATCH 4096
#define FDIM  512
#define NCLS  1000
#define MARGIN 0.3f
#define LAMBDA 0.01f
#define EPSV   1e-12f
#define NJT2  16         // CE partials per row: 8 j-tiles x 2 warp-halves

#define BM 128
#define BN 128

// ---- bf16 tiling (shared by triplet + CE) ----
#define BKT 64
#define NCHT (FDIM / BKT)                // 8
#define SSTRW 36                         // words per bf16 row (64 bf16 = 32 words + 4 pad)
#define TSTAGE_BYTES (256 * SSTRW * 4)   // 36864
#define TDYN_BYTES   (2 * TSTAGE_BYTES)  // 73728

#define NTILE (BATCH / BM)               // 32
#define NTRI  (NTILE * (NTILE + 1) / 2)  // 528

// ---------------- device scratch ----------------
__device__ float        g_sq[BATCH];
__device__ int          g_lab[BATCH];
__device__ unsigned int g_ap[BATCH];
__device__ unsigned int g_an[BATCH];
__device__ float        g_cent[BATCH];
__device__ float        g_pm[BATCH][NJT2];
__device__ float        g_ps[BATCH][NJT2];
__device__ float        g_ref[BATCH];
__device__ int          g_labmode;
__device__ __align__(16) uint4 g_ebf4[BATCH * FDIM / 8];   // E in bf16 (4 MB)
__device__ __align__(16) uint4 g_wbf4[NCLS * FDIM / 8];    // W in bf16 (1 MB)

// ---------------- helpers ----------------
__device__ __forceinline__ uint32_t smem_u32(const void* p) {
    uint32_t a;
    asm("{ .reg .u64 t; cvta.to.shared.u64 t, %1; cvt.u32.u64 %0, t; }" : "=r"(a) : "l"(p));
    return a;
}
__device__ __forceinline__ void cp16(uint32_t dst, const void* src) {
    asm volatile("cp.async.cg.shared.global [%0], [%1], 16;" :: "r"(dst), "l"(src));
}
__device__ __forceinline__ void cp_commit() {
    asm volatile("cp.async.commit_group;" ::: "memory");
}
template<int N> __device__ __forceinline__ void cp_wait() {
    asm volatile("cp.async.wait_group %0;" :: "n"(N) : "memory");
}
__device__ __forceinline__ void mma_bf16(float* c, const uint32_t* a, uint32_t b0, uint32_t b1) {
    asm volatile(
        "mma.sync.aligned.m16n8k16.row.col.f32.bf16.bf16.f32 "
        "{%0,%1,%2,%3}, {%4,%5,%6,%7}, {%8,%9}, {%0,%1,%2,%3};"
        : "+f"(c[0]), "+f"(c[1]), "+f"(c[2]), "+f"(c[3])
        : "r"(a[0]), "r"(a[1]), "r"(a[2]), "r"(a[3]), "r"(b0), "r"(b1));
}
__device__ __forceinline__ void ldsm_x4(uint32_t& r0, uint32_t& r1, uint32_t& r2, uint32_t& r3,
                                        uint32_t addr) {
    asm volatile("ldmatrix.sync.aligned.m8n8.x4.shared.b16 {%0,%1,%2,%3}, [%4];"
        : "=r"(r0), "=r"(r1), "=r"(r2), "=r"(r3) : "r"(addr));
}

// ---------------- fused label-detect (block 0) + W -> bf16 convert ----------------
__global__ void detect_wconv_kernel(const long long* __restrict__ lab64,
                                    const float* __restrict__ W) {
    if (blockIdx.x == 0) {
        __shared__ int bad;
        if (threadIdx.x == 0) bad = 0;
        __syncthreads();
        int mybad = 0;
        for (int i = threadIdx.x; i < 2048; i += blockDim.x) {
            long long v = lab64[i];
            if (v < 0 || v >= NCLS) mybad = 1;
        }
        if (mybad) atomicOr(&bad, 1);
        __syncthreads();
        if (threadIdx.x == 0) g_labmode = bad ? 1 : 0;
    }
    int idx = blockIdx.x * blockDim.x + threadIdx.x;   // 128000 float4s
    if (idx >= NCLS * FDIM / 4) return;
    float4 v = ((const float4*)W)[idx];
    __nv_bfloat162 h0 = __floats2bfloat162_rn(v.x, v.y);
    __nv_bfloat162 h1 = __floats2bfloat162_rn(v.z, v.w);
    uint2 packed;
    packed.x = *(uint32_t*)&h0;
    packed.y = *(uint32_t*)&h1;
    ((uint2*)g_wbf4)[idx] = packed;
}

// ---------------- fused prep + center + bf16 convert: one pass over E ----------------
__global__ void prep_center_kernel(const float* __restrict__ E, const void* __restrict__ labels,
                                   const float* __restrict__ Ctr) {
    int i = blockIdx.x;
    int t = threadIdx.x;    // 128
    __shared__ int slab;
    if (t == 0) {
        int lab;
        if (g_labmode == 0) lab = (int)((const long long*)labels)[i];
        else                lab = ((const int*)labels)[i];
        g_lab[i] = lab;
        slab = lab;
        g_ap[i] = 0u;
        g_an[i] = 0x7f800000u;
    }
    __syncthreads();
    int lab = slab;
    const float4* e4 = (const float4*)(E   + (size_t)i   * FDIM);
    const float4* c4 = (const float4*)(Ctr + (size_t)lab * FDIM);
    float4 v = e4[t];
    float4 cc = c4[t];
    float sq = v.x * v.x + v.y * v.y + v.z * v.z + v.w * v.w;
    float dx = v.x - cc.x, dy = v.y - cc.y, dz = v.z - cc.z, dw = v.w - cc.w;
    float cd = dx * dx + dy * dy + dz * dz + dw * dw;
    __nv_bfloat162 h0 = __floats2bfloat162_rn(v.x, v.y);
    __nv_bfloat162 h1 = __floats2bfloat162_rn(v.z, v.w);
    uint2 packed;
    packed.x = *(uint32_t*)&h0;
    packed.y = *(uint32_t*)&h1;
    ((uint2*)g_ebf4)[(size_t)i * (FDIM / 4) + t] = packed;

    for (int off = 16; off > 0; off >>= 1) {
        sq += __shfl_xor_sync(0xffffffff, sq, off);
        cd += __shfl_xor_sync(0xffffffff, cd, off);
    }
    __shared__ float wsq[4], wcd[4];
    if ((t & 31) == 0) { wsq[t >> 5] = sq; wcd[t >> 5] = cd; }
    __syncthreads();
    if (t == 0) {
        g_sq[i]   = wsq[0] + wsq[1] + wsq[2] + wsq[3];
        g_cent[i] = wcd[0] + wcd[1] + wcd[2] + wcd[3];
    }
}

// ---------------- triplet: symmetric bf16 Gram, ldmatrix fragments ----------------
__global__ __launch_bounds__(256, 2) void triplet_mma_kernel() {
    extern __shared__ float dynsm[];
    __shared__ float sQi[BM]; __shared__ int sLi[BM];
    __shared__ float sQj[BN]; __shared__ int sLj[BN];

    int rem = blockIdx.x, bi = 0;
    #pragma unroll 1
    for (;;) { int len = NTILE - bi; if (rem < len) break; rem -= len; bi++; }
    int bj = bi + rem;
    bool diag = (bi == bj);

    int t = threadIdx.x;
    int lane = t & 31, wid = t >> 5;
    int wm = wid >> 1, wn = wid & 1;
    int g = lane >> 2, tg = lane & 3;
    int i0 = bi * BM, j0 = bj * BN;

    uint32_t sbase = smem_u32(dynsm);
    const char* ebf = (const char*)g_ebf4;

    // per-lane ldmatrix address offsets (bytes)
    uint32_t a_lane = (uint32_t)(((lane & 15) * SSTRW + ((lane >> 4) ? 4 : 0)) * 4);
    uint32_t b_lane = (uint32_t)((((lane & 7) + ((lane >> 4) ? 8 : 0)) * SSTRW + ((lane & 8) ? 4 : 0)) * 4);
    uint32_t aA0 = (uint32_t)(wm * 32 * SSTRW * 4) + a_lane;
    uint32_t aB0 = (uint32_t)((128 + wn * 64) * SSTRW * 4) + b_lane;

    if (t < BM)            { sQi[t] = g_sq[i0 + t]; sLi[t] = g_lab[i0 + t]; }
    else if (t < BM + BN)  { int u = t - BM; sQj[u] = g_sq[j0 + u]; sLj[u] = g_lab[j0 + u]; }

    {
        #pragma unroll
        for (int s = 0; s < 8; s++) {
            int f = t + s * 256;
            int row = f >> 3, seg = f & 7;
            int grow = (row < 128) ? (i0 + row) : (j0 + row - 128);
            uint32_t dst = sbase + (uint32_t)(row * (SSTRW * 4) + seg * 16);
            cp16(dst, ebf + ((size_t)grow * FDIM + seg * 8) * 2);
        }
        cp_commit();
    }

    float acc[2][8][4];
    #pragma unroll
    for (int mt = 0; mt < 2; mt++)
        #pragma unroll
        for (int nt = 0; nt < 8; nt++)
            #pragma unroll
            for (int e = 0; e < 4; e++) acc[mt][nt][e] = 0.f;

    #pragma unroll 1
    for (int c = 0; c < NCHT; c++) {
        if (c + 1 < NCHT) {
            uint32_t ab = sbase + ((c + 1) & 1) * TSTAGE_BYTES;
            int kof = (c + 1) * BKT;
            #pragma unroll
            for (int s = 0; s < 8; s++) {
                int f = t + s * 256;
                int row = f >> 3, seg = f & 7;
                int grow = (row < 128) ? (i0 + row) : (j0 + row - 128);
                uint32_t dst = ab + (uint32_t)(row * (SSTRW * 4) + seg * 16);
                cp16(dst, ebf + ((size_t)grow * FDIM + kof + seg * 8) * 2);
            }
            cp_commit();
            cp_wait<1>();
        } else {
            cp_wait<0>();
        }
        __syncthreads();
        uint32_t stg = sbase + (c & 1) * TSTAGE_BYTES;
        #pragma unroll
        for (int k16 = 0; k16 < 4; k16++) {
            uint32_t w0b = (uint32_t)(k16 * 32);   // 8 words
            uint32_t af[2][4];
            ldsm_x4(af[0][0], af[0][1], af[0][2], af[0][3], stg + aA0 + w0b);
            ldsm_x4(af[1][0], af[1][1], af[1][2], af[1][3], stg + aA0 + 16 * SSTRW * 4 + w0b);
            #pragma unroll
            for (int p = 0; p < 4; p++) {
                uint32_t b0, b1, b2, b3;
                ldsm_x4(b0, b1, b2, b3, stg + aB0 + (uint32_t)(p * 16 * SSTRW * 4) + w0b);
                mma_bf16(acc[0][2 * p    ], af[0], b0, b1);
                mma_bf16(acc[1][2 * p    ], af[1], b0, b1);
                mma_bf16(acc[0][2 * p + 1], af[0], b2, b3);
                mma_bf16(acc[1][2 * p + 1], af[1], b2, b3);
            }
        }
        __syncthreads();
    }

    // ---- dual-sided epilogue ----
    float rap[4], ran[4];
    float cap[16], can[16];
    #pragma unroll
    for (int s4 = 0; s4 < 4; s4++) { rap[s4] = 0.f; ran[s4] = INFINITY; }
    #pragma unroll
    for (int cs = 0; cs < 16; cs++) { cap[cs] = 0.f; can[cs] = INFINITY; }

    #pragma unroll
    for (int mt = 0; mt < 2; mt++) {
        #pragma unroll
        for (int half = 0; half < 2; half++) {
            int lr = wm * 32 + mt * 16 + g + half * 8;
            float qi = sQi[lr]; int li = sLi[lr];
            int slot = mt * 2 + half;
            #pragma unroll
            for (int nt = 0; nt < 8; nt++) {
                #pragma unroll
                for (int e = 0; e < 2; e++) {
                    int lc = wn * 64 + nt * 8 + 2 * tg + e;
                    float d2 = qi + sQj[lc] - 2.f * acc[mt][nt][half * 2 + e];
                    float dist = sqrtf(fmaxf(d2, EPSV));
                    bool same = (sLj[lc] == li);
                    if (same) rap[slot] = fmaxf(rap[slot], dist);
                    else      ran[slot] = fminf(ran[slot], dist);
                    if (!diag) {
                        int cs = nt * 2 + e;
                        if (same) cap[cs] = fmaxf(cap[cs], dist);
                        else      can[cs] = fminf(can[cs], dist);
                    }
                }
            }
        }
    }

    #pragma unroll
    for (int s4 = 0; s4 < 4; s4++) {
        rap[s4] = fmaxf(rap[s4], __shfl_xor_sync(0xffffffff, rap[s4], 1));
        rap[s4] = fmaxf(rap[s4], __shfl_xor_sync(0xffffffff, rap[s4], 2));
        ran[s4] = fminf(ran[s4], __shfl_xor_sync(0xffffffff, ran[s4], 1));
        ran[s4] = fminf(ran[s4], __shfl_xor_sync(0xffffffff, ran[s4], 2));
    }
    if (tg == 0) {
        #pragma unroll
        for (int s4 = 0; s4 < 4; s4++) {
            int lr = wm * 32 + (s4 >> 1) * 16 + g + (s4 & 1) * 8;
            atomicMax(&g_ap[i0 + lr], __float_as_uint(rap[s4]));
            atomicMin(&g_an[i0 + lr], __float_as_uint(ran[s4]));
        }
    }
    if (!diag) {
        #pragma unroll
        for (int cs = 0; cs < 16; cs++) {
            cap[cs] = fmaxf(cap[cs], __shfl_xor_sync(0xffffffff, cap[cs], 4));
            cap[cs] = fmaxf(cap[cs], __shfl_xor_sync(0xffffffff, cap[cs], 8));
            cap[cs] = fmaxf(cap[cs], __shfl_xor_sync(0xffffffff, cap[cs], 16));
            can[cs] = fminf(can[cs], __shfl_xor_sync(0xffffffff, can[cs], 4));
            can[cs] = fminf(can[cs], __shfl_xor_sync(0xffffffff, can[cs], 8));
            can[cs] = fminf(can[cs], __shfl_xor_sync(0xffffffff, can[cs], 16));
        }
        if (lane < 4) {
            #pragma unroll
            for (int cs = 0; cs < 16; cs++) {
                int col = j0 + wn * 64 + (cs >> 1) * 8 + 2 * lane + (cs & 1);
                atomicMax(&g_ap[col], __float_as_uint(cap[cs]));
                atomicMin(&g_an[col], __float_as_uint(can[cs]));
            }
        }
    }
}

// ---------------- CE: bf16 logits, ldmatrix fragments ----------------
__global__ __launch_bounds__(256, 2) void ce_mma_kernel(const float* __restrict__ bvec) {
    extern __shared__ float dynsm[];
    __shared__ float sBias[BN];
    __shared__ int   sLab[BM];

    int t = threadIdx.x;
    int lane = t & 31, wid = t >> 5;
    int wm = wid >> 1, wn = wid & 1;
    int g = lane >> 2, tg = lane & 3;
    int i0 = blockIdx.x * BM, j0 = blockIdx.y * BN;
    int jt = blockIdx.y;

    uint32_t sbase = smem_u32(dynsm);
    const char* ebf = (const char*)g_ebf4;
    const char* wbf = (const char*)g_wbf4;

    uint32_t a_lane = (uint32_t)(((lane & 15) * SSTRW + ((lane >> 4) ? 4 : 0)) * 4);
    uint32_t b_lane = (uint32_t)((((lane & 7) + ((lane >> 4) ? 8 : 0)) * SSTRW + ((lane & 8) ? 4 : 0)) * 4);
    uint32_t aA0 = (uint32_t)(wm * 32 * SSTRW * 4) + a_lane;
    uint32_t aB0 = (uint32_t)((128 + wn * 64) * SSTRW * 4) + b_lane;

    if (t < BN)           { int cls = j0 + t; sBias[t] = bvec[cls < NCLS ? cls : NCLS - 1]; }
    else if (t < BN + BM) { sLab[t - BN] = g_lab[i0 + (t - BN)]; }

    {
        #pragma unroll
        for (int s = 0; s < 8; s++) {
            int f = t + s * 256;
            int row = f >> 3, seg = f & 7;
            uint32_t dst = sbase + (uint32_t)(row * (SSTRW * 4) + seg * 16);
            if (row < 128) {
                cp16(dst, ebf + ((size_t)(i0 + row) * FDIM + seg * 8) * 2);
            } else {
                int wr = j0 + row - 128; if (wr >= NCLS) wr = NCLS - 1;
                cp16(dst, wbf + ((size_t)wr * FDIM + seg * 8) * 2);
            }
        }
        cp_commit();
    }

    float acc[2][8][4];
    #pragma unroll
    for (int mt = 0; mt < 2; mt++)
        #pragma unroll
        for (int nt = 0; nt < 8; nt++)
            #pragma unroll
            for (int e = 0; e < 4; e++) acc[mt][nt][e] = 0.f;

    #pragma unroll 1
    for (int c = 0; c < NCHT; c++) {
        if (c + 1 < NCHT) {
            uint32_t ab = sbase + ((c + 1) & 1) * TSTAGE_BYTES;
            int kof = (c + 1) * BKT;
            #pragma unroll
            for (int s = 0; s < 8; s++) {
                int f = t + s * 256;
                int row = f >> 3, seg = f & 7;
                uint32_t dst = ab + (uint32_t)(row * (SSTRW * 4) + seg * 16);
                if (row < 128) {
                    cp16(dst, ebf + ((size_t)(i0 + row) * FDIM + kof + seg * 8) * 2);
                } else {
                    int wr = j0 + row - 128; if (wr >= NCLS) wr = NCLS - 1;
                    cp16(dst, wbf + ((size_t)wr * FDIM + kof + seg * 8) * 2);
                }
            }
            cp_commit();
            cp_wait<1>();
        } else {
            cp_wait<0>();
        }
        __syncthreads();
        uint32_t stg = sbase + (c & 1) * TSTAGE_BYTES;
        #pragma unroll
        for (int k16 = 0; k16 < 4; k16++) {
            uint32_t w0b = (uint32_t)(k16 * 32);
            uint32_t af[2][4];
            ldsm_x4(af[0][0], af[0][1], af[0][2], af[0][3], stg + aA0 + w0b);
            ldsm_x4(af[1][0], af[1][1], af[1][2], af[1][3], stg + aA0 + 16 * SSTRW * 4 + w0b);
            #pragma unroll
            for (int p = 0; p < 4; p++) {
                uint32_t b0, b1, b2, b3;
                ldsm_x4(b0, b1, b2, b3, stg + aB0 + (uint32_t)(p * 16 * SSTRW * 4) + w0b);
                mma_bf16(acc[0][2 * p    ], af[0], b0, b1);
                mma_bf16(acc[1][2 * p    ], af[1], b0, b1);
                mma_bf16(acc[0][2 * p + 1], af[0], b2, b3);
                mma_bf16(acc[1][2 * p + 1], af[1], b2, b3);
            }
        }
        __syncthreads();
    }

    // epilogue: masked bias-add, per-(row, warp-half) partial (max, sumexp)
    #pragma unroll
    for (int mt = 0; mt < 2; mt++) {
        #pragma unroll
        for (int half = 0; half < 2; half++) {
            int lr = wm * 32 + mt * 16 + g + half * 8;
            int irow = i0 + lr;
            int lab  = sLab[lr];
            float v[16];
            float m = -INFINITY;
            #pragma unroll
            for (int nt = 0; nt < 8; nt++) {
                #pragma unroll
                for (int e = 0; e < 2; e++) {
                    int lc  = wn * 64 + nt * 8 + 2 * tg + e;
                    int col = j0 + lc;
                    float x = (col < NCLS) ? (acc[mt][nt][half * 2 + e] + sBias[lc]) : -INFINITY;
                    if (col == lab) g_ref[irow] = x;
                    v[nt * 2 + e] = x;
                    m = fmaxf(m, x);
                }
            }
            m = fmaxf(m, __shfl_xor_sync(0xffffffff, m, 1));
            m = fmaxf(m, __shfl_xor_sync(0xffffffff, m, 2));
            float s = 0.f;
            #pragma unroll
            for (int q = 0; q < 16; q++) s += __expf(v[q] - m);
            s += __shfl_xor_sync(0xffffffff, s, 1);
            s += __shfl_xor_sync(0xffffffff, s, 2);
            if (tg == 0) { g_pm[irow][jt * 2 + wn] = m; g_ps[irow][jt * 2 + wn] = s; }
        }
    }
}

// ---------------- final: CE merge + total loss (deterministic) ----------------
__global__ void final_kernel(float* __restrict__ out) {
    int t = threadIdx.x;   // 1024
    float l = 0.f;
    for (int i = t; i < BATCH; i += 1024) {
        float M = -INFINITY;
        #pragma unroll
        for (int k = 0; k < NJT2; k++) M = fmaxf(M, g_pm[i][k]);
        float S = 0.f;
        #pragma unroll
        for (int k = 0; k < NJT2; k++) S += g_ps[i][k] * expf(g_pm[i][k] - M);
        float ce = M + logf(S) - g_ref[i];
        float ap = __uint_as_float(g_ap[i]);
        float an = __uint_as_float(g_an[i]);
        l += fmaxf(ap - an + MARGIN, 0.f) + LAMBDA * g_cent[i] + ce;
    }
    __shared__ float red[1024];
    red[t] = l;
    __syncthreads();
    for (int off = 512; off > 0; off >>= 1) {
        if (t < off) red[t] += red[t + off];
        __syncthreads();
    }
    if (t == 0) out[0] = red[0] / (float)BATCH;
}

// ---------------- launch ----------------
extern "C" void kernel_launch(void* const* d_in, const int* in_sizes, int n_in,
                              void* d_out, int out_size) {
    const float* E    = (const float*)d_in[0];
    const void*  labs = d_in[1];
    const float* Ctr  = (const float*)d_in[2];
    const float* W    = (const float*)d_in[3];
    const float* bvec = (const float*)d_in[4];
    float* out = (float*)d_out;

    cudaFuncSetAttribute(triplet_mma_kernel, cudaFuncAttributeMaxDynamicSharedMemorySize, TDYN_BYTES);
    cudaFuncSetAttribute(ce_mma_kernel,      cudaFuncAttributeMaxDynamicSharedMemorySize, TDYN_BYTES);

    detect_wconv_kernel<<<(NCLS * FDIM / 4 + 255) / 256, 256>>>((const long long*)labs, W);
    prep_center_kernel<<<BATCH, 128>>>(E, labs, Ctr);
    triplet_mma_kernel<<<NTRI, 256, TDYN_BYTES>>>();
    ce_mma_kernel<<<dim3(BATCH / BM, 1024 / BN), 256, TDYN_BYTES>>>(bvec);
    final_kernel<<<1, 1024>>>(out);
}

// round 15
// speedup vs baseline: 11.7630x; 1.0027x over previous
#include <cuda_runtime.h>
#include <cuda_bf16.h>
#include <math.h>
#include <stdint.h>

#define BATCH 4096
#define FDIM  512
#define NCLS  1000
#define MARGIN 0.3f
#define LAMBDA 0.01f
#define EPSV   1e-12f
#define NJT2  16         // CE partials per row: 8 j-tiles x 2 warp-halves

#define BM 128
#define BN 128

// ---- bf16 tiling (shared by triplet + CE) ----
#define BKT 64
#define NCHT (FDIM / BKT)                // 8
#define SSTRW 36                         // words per bf16 row (64 bf16 = 32 words + 4 pad)
#define TSTAGE_BYTES (256 * SSTRW * 4)   // 36864
#define TDYN_BYTES   (2 * TSTAGE_BYTES)  // 73728

#define NTILE (BATCH / BM)               // 32
#define NTRI  (NTILE * (NTILE + 1) / 2)  // 528

// ---------------- device scratch ----------------
__device__ float        g_sq[BATCH];
__device__ int          g_lab[BATCH];
__device__ unsigned int g_ap[BATCH];
__device__ unsigned int g_an[BATCH];
__device__ float        g_cent[BATCH];
__device__ float        g_pm[BATCH][NJT2];
__device__ float        g_ps[BATCH][NJT2];
__device__ float        g_ref[BATCH];
__device__ int          g_labmode;
__device__ __align__(16) uint4 g_ebf4[BATCH * FDIM / 8];   // E in bf16 (4 MB)
__device__ __align__(16) uint4 g_wbf4[NCLS * FDIM / 8];    // W in bf16 (1 MB)

// ---------------- helpers ----------------
__device__ __forceinline__ uint32_t smem_u32(const void* p) {
    uint32_t a;
    asm("{ .reg .u64 t; cvta.to.shared.u64 t, %1; cvt.u32.u64 %0, t; }" : "=r"(a) : "l"(p));
    return a;
}
__device__ __forceinline__ void cp16(uint32_t dst, const void* src) {
    asm volatile("cp.async.cg.shared.global [%0], [%1], 16;" :: "r"(dst), "l"(src));
}
__device__ __forceinline__ void cp_commit() {
    asm volatile("cp.async.commit_group;" ::: "memory");
}
template<int N> __device__ __forceinline__ void cp_wait() {
    asm volatile("cp.async.wait_group %0;" :: "n"(N) : "memory");
}
__device__ __forceinline__ void mma_bf16(float* c, const uint32_t* a, uint32_t b0, uint32_t b1) {
    asm volatile(
        "mma.sync.aligned.m16n8k16.row.col.f32.bf16.bf16.f32 "
        "{%0,%1,%2,%3}, {%4,%5,%6,%7}, {%8,%9}, {%0,%1,%2,%3};"
        : "+f"(c[0]), "+f"(c[1]), "+f"(c[2]), "+f"(c[3])
        : "r"(a[0]), "r"(a[1]), "r"(a[2]), "r"(a[3]), "r"(b0), "r"(b1));
}
__device__ __forceinline__ void ldsm_x4(uint32_t& r0, uint32_t& r1, uint32_t& r2, uint32_t& r3,
                                        uint32_t addr) {
    asm volatile("ldmatrix.sync.aligned.m8n8.x4.shared.b16 {%0,%1,%2,%3}, [%4];"
        : "=r"(r0), "=r"(r1), "=r"(r2), "=r"(r3) : "r"(addr));
}

// ---------------- fused label-detect (block 0) + W -> bf16 convert ----------------
__global__ void detect_wconv_kernel(const long long* __restrict__ lab64,
                                    const float* __restrict__ W) {
    if (blockIdx.x == 0) {
        __shared__ int bad;
        if (threadIdx.x == 0) bad = 0;
        __syncthreads();
        int mybad = 0;
        for (int i = threadIdx.x; i < 2048; i += blockDim.x) {
            long long v = lab64[i];
            if (v < 0 || v >= NCLS) mybad = 1;
        }
        if (mybad) atomicOr(&bad, 1);
        __syncthreads();
        if (threadIdx.x == 0) g_labmode = bad ? 1 : 0;
    }
    int idx = blockIdx.x * blockDim.x + threadIdx.x;   // 128000 float4s
    if (idx >= NCLS * FDIM / 4) return;
    float4 v = ((const float4*)W)[idx];
    __nv_bfloat162 h0 = __floats2bfloat162_rn(v.x, v.y);
    __nv_bfloat162 h1 = __floats2bfloat162_rn(v.z, v.w);
    uint2 packed;
    packed.x = *(uint32_t*)&h0;
    packed.y = *(uint32_t*)&h1;
    ((uint2*)g_wbf4)[idx] = packed;
}

// ---------------- fused prep + center + bf16 convert: one pass over E ----------------
__global__ void prep_center_kernel(const float* __restrict__ E, const void* __restrict__ labels,
                                   const float* __restrict__ Ctr) {
    int i = blockIdx.x;
    int t = threadIdx.x;    // 128
    __shared__ int slab;
    if (t == 0) {
        int lab;
        if (g_labmode == 0) lab = (int)((const long long*)labels)[i];
        else                lab = ((const int*)labels)[i];
        g_lab[i] = lab;
        slab = lab;
        g_ap[i] = 0u;
        g_an[i] = 0x7f800000u;
    }
    __syncthreads();
    int lab = slab;
    const float4* e4 = (const float4*)(E   + (size_t)i   * FDIM);
    const float4* c4 = (const float4*)(Ctr + (size_t)lab * FDIM);
    float4 v = e4[t];
    float4 cc = c4[t];
    float sq = v.x * v.x + v.y * v.y + v.z * v.z + v.w * v.w;
    float dx = v.x - cc.x, dy = v.y - cc.y, dz = v.z - cc.z, dw = v.w - cc.w;
    float cd = dx * dx + dy * dy + dz * dz + dw * dw;
    __nv_bfloat162 h0 = __floats2bfloat162_rn(v.x, v.y);
    __nv_bfloat162 h1 = __floats2bfloat162_rn(v.z, v.w);
    uint2 packed;
    packed.x = *(uint32_t*)&h0;
    packed.y = *(uint32_t*)&h1;
    ((uint2*)g_ebf4)[(size_t)i * (FDIM / 4) + t] = packed;

    for (int off = 16; off > 0; off >>= 1) {
        sq += __shfl_xor_sync(0xffffffff, sq, off);
        cd += __shfl_xor_sync(0xffffffff, cd, off);
    }
    __shared__ float wsq[4], wcd[4];
    if ((t & 31) == 0) { wsq[t >> 5] = sq; wcd[t >> 5] = cd; }
    __syncthreads();
    if (t == 0) {
        g_sq[i]   = wsq[0] + wsq[1] + wsq[2] + wsq[3];
        g_cent[i] = wcd[0] + wcd[1] + wcd[2] + wcd[3];
    }
}

// ---------------- triplet: symmetric bf16 Gram, ldmatrix, single-sync pipeline ----------------
__global__ __launch_bounds__(256, 2) void triplet_mma_kernel() {
    extern __shared__ float dynsm[];
    __shared__ float sQi[BM]; __shared__ int sLi[BM];
    __shared__ float sQj[BN]; __shared__ int sLj[BN];

    int rem = blockIdx.x, bi = 0;
    #pragma unroll 1
    for (;;) { int len = NTILE - bi; if (rem < len) break; rem -= len; bi++; }
    int bj = bi + rem;
    bool diag = (bi == bj);

    int t = threadIdx.x;
    int lane = t & 31, wid = t >> 5;
    int wm = wid >> 1, wn = wid & 1;
    int g = lane >> 2, tg = lane & 3;
    int i0 = bi * BM, j0 = bj * BN;

    uint32_t sbase = smem_u32(dynsm);
    const char* ebf = (const char*)g_ebf4;

    uint32_t a_lane = (uint32_t)(((lane & 15) * SSTRW + ((lane >> 4) ? 4 : 0)) * 4);
    uint32_t b_lane = (uint32_t)((((lane & 7) + ((lane >> 4) ? 8 : 0)) * SSTRW + ((lane & 8) ? 4 : 0)) * 4);
    uint32_t aA0 = (uint32_t)(wm * 32 * SSTRW * 4) + a_lane;
    uint32_t aB0 = (uint32_t)((128 + wn * 64) * SSTRW * 4) + b_lane;

    if (t < BM)            { sQi[t] = g_sq[i0 + t]; sLi[t] = g_lab[i0 + t]; }
    else if (t < BM + BN)  { int u = t - BM; sQj[u] = g_sq[j0 + u]; sLj[u] = g_lab[j0 + u]; }

    // prologue: chunk 0 -> stage 0
    {
        #pragma unroll
        for (int s = 0; s < 8; s++) {
            int f = t + s * 256;
            int row = f >> 3, seg = f & 7;
            int grow = (row < 128) ? (i0 + row) : (j0 + row - 128);
            uint32_t dst = sbase + (uint32_t)(row * (SSTRW * 4) + seg * 16);
            cp16(dst, ebf + ((size_t)grow * FDIM + seg * 8) * 2);
        }
        cp_commit();
    }

    float acc[2][8][4];
    #pragma unroll
    for (int mt = 0; mt < 2; mt++)
        #pragma unroll
        for (int nt = 0; nt < 8; nt++)
            #pragma unroll
            for (int e = 0; e < 4; e++) acc[mt][nt][e] = 0.f;

    // single-sync double-buffer: cp(c+1) issued AFTER the sync, overwriting the
    // buffer last read in iteration c-1 (sync proves all warps left it).
    #pragma unroll 1
    for (int c = 0; c < NCHT; c++) {
        cp_wait<0>();
        __syncthreads();
        if (c + 1 < NCHT) {
            uint32_t ab = sbase + ((c + 1) & 1) * TSTAGE_BYTES;
            int kof = (c + 1) * BKT;
            #pragma unroll
            for (int s = 0; s < 8; s++) {
                int f = t + s * 256;
                int row = f >> 3, seg = f & 7;
                int grow = (row < 128) ? (i0 + row) : (j0 + row - 128);
                uint32_t dst = ab + (uint32_t)(row * (SSTRW * 4) + seg * 16);
                cp16(dst, ebf + ((size_t)grow * FDIM + kof + seg * 8) * 2);
            }
            cp_commit();
        }
        uint32_t stg = sbase + (c & 1) * TSTAGE_BYTES;
        #pragma unroll
        for (int k16 = 0; k16 < 4; k16++) {
            uint32_t w0b = (uint32_t)(k16 * 32);   // 8 words
            uint32_t af[2][4];
            ldsm_x4(af[0][0], af[0][1], af[0][2], af[0][3], stg + aA0 + w0b);
            ldsm_x4(af[1][0], af[1][1], af[1][2], af[1][3], stg + aA0 + 16 * SSTRW * 4 + w0b);
            #pragma unroll
            for (int p = 0; p < 4; p++) {
                uint32_t b0, b1, b2, b3;
                ldsm_x4(b0, b1, b2, b3, stg + aB0 + (uint32_t)(p * 16 * SSTRW * 4) + w0b);
                mma_bf16(acc[0][2 * p    ], af[0], b0, b1);
                mma_bf16(acc[1][2 * p    ], af[1], b0, b1);
                mma_bf16(acc[0][2 * p + 1], af[0], b2, b3);
                mma_bf16(acc[1][2 * p + 1], af[1], b2, b3);
            }
        }
    }

    // ---- dual-sided epilogue ----
    float rap[4], ran[4];
    float cap[16], can[16];
    #pragma unroll
    for (int s4 = 0; s4 < 4; s4++) { rap[s4] = 0.f; ran[s4] = INFINITY; }
    #pragma unroll
    for (int cs = 0; cs < 16; cs++) { cap[cs] = 0.f; can[cs] = INFINITY; }

    #pragma unroll
    for (int mt = 0; mt < 2; mt++) {
        #pragma unroll
        for (int half = 0; half < 2; half++) {
            int lr = wm * 32 + mt * 16 + g + half * 8;
            float qi = sQi[lr]; int li = sLi[lr];
            int slot = mt * 2 + half;
            #pragma unroll
            for (int nt = 0; nt < 8; nt++) {
                #pragma unroll
                for (int e = 0; e < 2; e++) {
                    int lc = wn * 64 + nt * 8 + 2 * tg + e;
                    float d2 = qi + sQj[lc] - 2.f * acc[mt][nt][half * 2 + e];
                    float dist = sqrtf(fmaxf(d2, EPSV));
                    bool same = (sLj[lc] == li);
                    if (same) rap[slot] = fmaxf(rap[slot], dist);
                    else      ran[slot] = fminf(ran[slot], dist);
                    if (!diag) {
                        int cs = nt * 2 + e;
                        if (same) cap[cs] = fmaxf(cap[cs], dist);
                        else      can[cs] = fminf(can[cs], dist);
                    }
                }
            }
        }
    }

    #pragma unroll
    for (int s4 = 0; s4 < 4; s4++) {
        rap[s4] = fmaxf(rap[s4], __shfl_xor_sync(0xffffffff, rap[s4], 1));
        rap[s4] = fmaxf(rap[s4], __shfl_xor_sync(0xffffffff, rap[s4], 2));
        ran[s4] = fminf(ran[s4], __shfl_xor_sync(0xffffffff, ran[s4], 1));
        ran[s4] = fminf(ran[s4], __shfl_xor_sync(0xffffffff, ran[s4], 2));
    }
    if (tg == 0) {
        #pragma unroll
        for (int s4 = 0; s4 < 4; s4++) {
            int lr = wm * 32 + (s4 >> 1) * 16 + g + (s4 & 1) * 8;
            atomicMax(&g_ap[i0 + lr], __float_as_uint(rap[s4]));
            atomicMin(&g_an[i0 + lr], __float_as_uint(ran[s4]));
        }
    }
    if (!diag) {
        #pragma unroll
        for (int cs = 0; cs < 16; cs++) {
            cap[cs] = fmaxf(cap[cs], __shfl_xor_sync(0xffffffff, cap[cs], 4));
            cap[cs] = fmaxf(cap[cs], __shfl_xor_sync(0xffffffff, cap[cs], 8));
            cap[cs] = fmaxf(cap[cs], __shfl_xor_sync(0xffffffff, cap[cs], 16));
            can[cs] = fminf(can[cs], __shfl_xor_sync(0xffffffff, can[cs], 4));
            can[cs] = fminf(can[cs], __shfl_xor_sync(0xffffffff, can[cs], 8));
            can[cs] = fminf(can[cs], __shfl_xor_sync(0xffffffff, can[cs], 16));
        }
        if (lane < 4) {
            #pragma unroll
            for (int cs = 0; cs < 16; cs++) {
                int col = j0 + wn * 64 + (cs >> 1) * 8 + 2 * lane + (cs & 1);
                atomicMax(&g_ap[col], __float_as_uint(cap[cs]));
                atomicMin(&g_an[col], __float_as_uint(can[cs]));
            }
        }
    }
}

// ---------------- CE: bf16 logits, ldmatrix, single-sync pipeline ----------------
__global__ __launch_bounds__(256, 2) void ce_mma_kernel(const float* __restrict__ bvec) {
    extern __shared__ float dynsm[];
    __shared__ float sBias[BN];
    __shared__ int   sLab[BM];

    int t = threadIdx.x;
    int lane = t & 31, wid = t >> 5;
    int wm = wid >> 1, wn = wid & 1;
    int g = lane >> 2, tg = lane & 3;
    int i0 = blockIdx.x * BM, j0 = blockIdx.y * BN;
    int jt = blockIdx.y;

    uint32_t sbase = smem_u32(dynsm);
    const char* ebf = (const char*)g_ebf4;
    const char* wbf = (const char*)g_wbf4;

    uint32_t a_lane = (uint32_t)(((lane & 15) * SSTRW + ((lane >> 4) ? 4 : 0)) * 4);
    uint32_t b_lane = (uint32_t)((((lane & 7) + ((lane >> 4) ? 8 : 0)) * SSTRW + ((lane & 8) ? 4 : 0)) * 4);
    uint32_t aA0 = (uint32_t)(wm * 32 * SSTRW * 4) + a_lane;
    uint32_t aB0 = (uint32_t)((128 + wn * 64) * SSTRW * 4) + b_lane;

    if (t < BN)           { int cls = j0 + t; sBias[t] = bvec[cls < NCLS ? cls : NCLS - 1]; }
    else if (t < BN + BM) { sLab[t - BN] = g_lab[i0 + (t - BN)]; }

    {
        #pragma unroll
        for (int s = 0; s < 8; s++) {
            int f = t + s * 256;
            int row = f >> 3, seg = f & 7;
            uint32_t dst = sbase + (uint32_t)(row * (SSTRW * 4) + seg * 16);
            if (row < 128) {
                cp16(dst, ebf + ((size_t)(i0 + row) * FDIM + seg * 8) * 2);
            } else {
                int wr = j0 + row - 128; if (wr >= NCLS) wr = NCLS - 1;
                cp16(dst, wbf + ((size_t)wr * FDIM + seg * 8) * 2);
            }
        }
        cp_commit();
    }

    float acc[2][8][4];
    #pragma unroll
    for (int mt = 0; mt < 2; mt++)
        #pragma unroll
        for (int nt = 0; nt < 8; nt++)
            #pragma unroll
            for (int e = 0; e < 4; e++) acc[mt][nt][e] = 0.f;

    #pragma unroll 1
    for (int c = 0; c < NCHT; c++) {
        cp_wait<0>();
        __syncthreads();
        if (c + 1 < NCHT) {
            uint32_t ab = sbase + ((c + 1) & 1) * TSTAGE_BYTES;
            int kof = (c + 1) * BKT;
            #pragma unroll
            for (int s = 0; s < 8; s++) {
                int f = t + s * 256;
                int row = f >> 3, seg = f & 7;
                uint32_t dst = ab + (uint32_t)(row * (SSTRW * 4) + seg * 16);
                if (row < 128) {
                    cp16(dst, ebf + ((size_t)(i0 + row) * FDIM + kof + seg * 8) * 2);
                } else {
                    int wr = j0 + row - 128; if (wr >= NCLS) wr = NCLS - 1;
                    cp16(dst, wbf + ((size_t)wr * FDIM + kof + seg * 8) * 2);
                }
            }
            cp_commit();
        }
        uint32_t stg = sbase + (c & 1) * TSTAGE_BYTES;
        #pragma unroll
        for (int k16 = 0; k16 < 4; k16++) {
            uint32_t w0b = (uint32_t)(k16 * 32);
            uint32_t af[2][4];
            ldsm_x4(af[0][0], af[0][1], af[0][2], af[0][3], stg + aA0 + w0b);
            ldsm_x4(af[1][0], af[1][1], af[1][2], af[1][3], stg + aA0 + 16 * SSTRW * 4 + w0b);
            #pragma unroll
            for (int p = 0; p < 4; p++) {
                uint32_t b0, b1, b2, b3;
                ldsm_x4(b0, b1, b2, b3, stg + aB0 + (uint32_t)(p * 16 * SSTRW * 4) + w0b);
                mma_bf16(acc[0][2 * p    ], af[0], b0, b1);
                mma_bf16(acc[1][2 * p    ], af[1], b0, b1);
                mma_bf16(acc[0][2 * p + 1], af[0], b2, b3);
                mma_bf16(acc[1][2 * p + 1], af[1], b2, b3);
            }
        }
    }

    // epilogue: masked bias-add, per-(row, warp-half) partial (max, sumexp)
    #pragma unroll
    for (int mt = 0; mt < 2; mt++) {
        #pragma unroll
        for (int half = 0; half < 2; half++) {
            int lr = wm * 32 + mt * 16 + g + half * 8;
            int irow = i0 + lr;
            int lab  = sLab[lr];
            float v[16];
            float m = -INFINITY;
            #pragma unroll
            for (int nt = 0; nt < 8; nt++) {
                #pragma unroll
                for (int e = 0; e < 2; e++) {
                    int lc  = wn * 64 + nt * 8 + 2 * tg + e;
                    int col = j0 + lc;
                    float x = (col < NCLS) ? (acc[mt][nt][half * 2 + e] + sBias[lc]) : -INFINITY;
                    if (col == lab) g_ref[irow] = x;
                    v[nt * 2 + e] = x;
                    m = fmaxf(m, x);
                }
            }
            m = fmaxf(m, __shfl_xor_sync(0xffffffff, m, 1));
            m = fmaxf(m, __shfl_xor_sync(0xffffffff, m, 2));
            float s = 0.f;
            #pragma unroll
            for (int q = 0; q < 16; q++) s += __expf(v[q] - m);
            s += __shfl_xor_sync(0xffffffff, s, 1);
            s += __shfl_xor_sync(0xffffffff, s, 2);
            if (tg == 0) { g_pm[irow][jt * 2 + wn] = m; g_ps[irow][jt * 2 + wn] = s; }
        }
    }
}

// ---------------- final: CE merge + total loss (deterministic) ----------------
__global__ void final_kernel(float* __restrict__ out) {
    int t = threadIdx.x;   // 1024
    float l = 0.f;
    for (int i = t; i < BATCH; i += 1024) {
        float M = -INFINITY;
        #pragma unroll
        for (int k = 0; k < NJT2; k++) M = fmaxf(M, g_pm[i][k]);
        float S = 0.f;
        #pragma unroll
        for (int k = 0; k < NJT2; k++) S += g_ps[i][k] * expf(g_pm[i][k] - M);
        float ce = M + logf(S) - g_ref[i];
        float ap = __uint_as_float(g_ap[i]);
        float an = __uint_as_float(g_an[i]);
        l += fmaxf(ap - an + MARGIN, 0.f) + LAMBDA * g_cent[i] + ce;
    }
    __shared__ float red[1024];
    red[t] = l;
    __syncthreads();
    for (int off = 512; off > 0; off >>= 1) {
        if (t < off) red[t] += red[t + off];
        __syncthreads();
    }
    if (t == 0) out[0] = red[0] / (float)BATCH;
}

// ---------------- launch ----------------
extern "C" void kernel_launch(void* const* d_in, const int* in_sizes, int n_in,
                              void* d_out, int out_size) {
    const float* E    = (const float*)d_in[0];
    const void*  labs = d_in[1];
    const float* Ctr  = (const float*)d_in[2];
    const float* W    = (const float*)d_in[3];
    const float* bvec = (const float*)d_in[4];
    float* out = (float*)d_out;

    cudaFuncSetAttribute(triplet_mma_kernel, cudaFuncAttributeMaxDynamicSharedMemorySize, TDYN_BYTES);
    cudaFuncSetAttribute(ce_mma_kernel,      cudaFuncAttributeMaxDynamicSharedMemorySize, TDYN_BYTES);

    detect_wconv_kernel<<<(NCLS * FDIM / 4 + 255) / 256, 256>>>((const long long*)labs, W);
    prep_center_kernel<<<BATCH, 128>>>(E, labs, Ctr);
    triplet_mma_kernel<<<NTRI, 256, TDYN_BYTES>>>();
    ce_mma_kernel<<<dim3(BATCH / BM, 1024 / BN), 256, TDYN_BYTES>>>(bvec);
    final_kernel<<<1, 1024>>>(out);
}